// round 10
// baseline (speedup 1.0000x reference)
#include <cuda_runtime.h>
#include <math.h>
#include <stdint.h>

#define T_STEPS 1000
#define BATCH   64
#define IN_DIM  512
#define HID     1024
#define OUT_DIM 64
#define NY      65
#define E_SZ    819
#define ALPHA   0.2f
#define OMALPHA 0.8f
#define NCTA 128
#define OPAD 80
#define WSTR 1028            // padded j-row stride

__device__ float g_xq[(size_t)T_STEPS * HID * BATCH];     // [t][h][b]
__device__ float g_outAll[(size_t)T_STEPS * HID * BATCH]; // [t][j][b] (for readout)
__device__ float g_outT[(size_t)T_STEPS * BATCH * HID];   // [t][b][j] (for rnn)
__device__ float g_eWhP2[32 * 32 * WSTR];                 // [hgrp][h&31][j pad]
__device__ float g_eWoT[HID * OPAD];                      // [j][o]
__device__ unsigned g_count;
__device__ volatile unsigned g_flag;                      // 1000 flips (even) -> replay safe

__device__ __forceinline__ unsigned long long pk2(float x, float y) {
    unsigned long long r;
    asm("mov.b64 %0, {%1, %2};" : "=l"(r) : "r"(__float_as_uint(x)), "r"(__float_as_uint(y)));
    return r;
}
__device__ __forceinline__ void upk2(unsigned long long v, float &x, float &y) {
    unsigned xi, yi;
    asm("mov.b64 {%0, %1}, %2;" : "=r"(xi), "=r"(yi) : "l"(v));
    x = __uint_as_float(xi); y = __uint_as_float(yi);
}
__device__ __forceinline__ unsigned long long ffma2(unsigned long long a,
                                                    unsigned long long b,
                                                    unsigned long long c) {
    unsigned long long d;
    asm("fma.rn.f32x2 %0, %1, %2, %3;" : "=l"(d) : "l"(a), "l"(b), "l"(c));
    return d;
}
__device__ __forceinline__ unsigned long long fadd2(unsigned long long a,
                                                    unsigned long long b) {
    unsigned long long d;
    asm("add.rn.f32x2 %0, %1, %2;" : "=l"(d) : "l"(a), "l"(b));
    return d;
}

__global__ void prep_kernel(const float* __restrict__ Wh,
                            const float* __restrict__ Wo,
                            const float* __restrict__ Wv) {
    int idx = blockIdx.x * blockDim.x + threadIdx.x;
    const int N1 = HID * HID;
    if (idx < N1) {
        int h = idx >> 10, j = idx & 1023;
        float v = Wh[idx];
        v = v > 0.f ? v : 0.f;
        float s = (j < E_SZ) ? 1.f : -1.f;
        v = (h == j) ? 0.f : v * s;
        g_eWhP2[(size_t)(h >> 5) * (32 * WSTR) + (size_t)(h & 31) * WSTR + j] = v;
    } else if (idx < N1 + NY * HID) {
        int i2 = idx - N1;
        int o = i2 >> 10, j = i2 & 1023;
        float v = (o < OUT_DIM) ? Wo[o * HID + j] : Wv[j];
        v = v > 0.f ? v : 0.f;
        if (j >= E_SZ) v = 0.f;
        g_eWoT[(size_t)j * OPAD + o] = v;
    }
}

// ---- phase 1 (proven): g_xq[t][h][b] = sum_k x[t][b][k]*relu(Wx[h][k])
__global__ __launch_bounds__(256) void xproj_kernel(const float* __restrict__ x,
                                                    const float* __restrict__ Wx) {
    __shared__ float As[16][64];
    __shared__ float Bs[16][128];
    const int t  = blockIdx.y;
    const int h0 = blockIdx.x * 128;
    const int tid = threadIdx.x;
    const int tx = tid & 15;
    const int ty = tid >> 4;

    unsigned long long acc[4][4];
#pragma unroll
    for (int i = 0; i < 4; i++)
#pragma unroll
        for (int p = 0; p < 4; p++) acc[i][p] = 0ull;

    const float* xb = x + (size_t)t * BATCH * IN_DIM;
    const int bb  = tid >> 2;
    const int kk4 = (tid & 3) << 2;
    const int hh  = tid & 127;
    const int kq  = (tid >> 7) << 3;

    for (int k0 = 0; k0 < IN_DIM; k0 += 16) {
        __syncthreads();
        float4 av = *(const float4*)&xb[(size_t)bb * IN_DIM + k0 + kk4];
        As[kk4 + 0][bb] = av.x; As[kk4 + 1][bb] = av.y;
        As[kk4 + 2][bb] = av.z; As[kk4 + 3][bb] = av.w;
        const float* wrow = Wx + (size_t)(h0 + hh) * IN_DIM + k0 + kq;
        float4 w0 = *(const float4*)wrow;
        float4 w1 = *(const float4*)(wrow + 4);
        Bs[kq + 0][hh] = fmaxf(w0.x, 0.f); Bs[kq + 1][hh] = fmaxf(w0.y, 0.f);
        Bs[kq + 2][hh] = fmaxf(w0.z, 0.f); Bs[kq + 3][hh] = fmaxf(w0.w, 0.f);
        Bs[kq + 4][hh] = fmaxf(w1.x, 0.f); Bs[kq + 5][hh] = fmaxf(w1.y, 0.f);
        Bs[kq + 6][hh] = fmaxf(w1.z, 0.f); Bs[kq + 7][hh] = fmaxf(w1.w, 0.f);
        __syncthreads();
#pragma unroll
        for (int kk = 0; kk < 16; kk++) {
            float4 a = *(const float4*)&As[kk][tx << 2];
            ulonglong2 wA = *(const ulonglong2*)&Bs[kk][(ty << 3)];
            ulonglong2 wB = *(const ulonglong2*)&Bs[kk][(ty << 3) + 4];
            unsigned long long a0 = pk2(a.x, a.x), a1 = pk2(a.y, a.y);
            unsigned long long a2 = pk2(a.z, a.z), a3 = pk2(a.w, a.w);
            acc[0][0] = ffma2(a0, wA.x, acc[0][0]); acc[0][1] = ffma2(a0, wA.y, acc[0][1]);
            acc[0][2] = ffma2(a0, wB.x, acc[0][2]); acc[0][3] = ffma2(a0, wB.y, acc[0][3]);
            acc[1][0] = ffma2(a1, wA.x, acc[1][0]); acc[1][1] = ffma2(a1, wA.y, acc[1][1]);
            acc[1][2] = ffma2(a1, wB.x, acc[1][2]); acc[1][3] = ffma2(a1, wB.y, acc[1][3]);
            acc[2][0] = ffma2(a2, wA.x, acc[2][0]); acc[2][1] = ffma2(a2, wA.y, acc[2][1]);
            acc[2][2] = ffma2(a2, wB.x, acc[2][2]); acc[2][3] = ffma2(a2, wB.y, acc[2][3]);
            acc[3][0] = ffma2(a3, wA.x, acc[3][0]); acc[3][1] = ffma2(a3, wA.y, acc[3][1]);
            acc[3][2] = ffma2(a3, wB.x, acc[3][2]); acc[3][3] = ffma2(a3, wB.y, acc[3][3]);
        }
    }
    float* xqo = g_xq + (size_t)t * (HID * BATCH);
#pragma unroll
    for (int i = 0; i < 4; i++) {
        int b = (tx << 2) + i;
#pragma unroll
        for (int p = 0; p < 4; p++) {
            float f0, f1; upk2(acc[i][p], f0, f1);
            int h = h0 + (ty << 3) + (p << 1);
            xqo[(size_t)h * 64 + b]       = f0;
            xqo[(size_t)(h + 1) * 64 + b] = f1;
        }
    }
}

__device__ __forceinline__ void grid_barrier(unsigned &sense) {
    sense ^= 1u;
    __threadfence();
    __syncthreads();
    if (threadIdx.x == 0) {
        unsigned old = atomicAdd(&g_count, 1u);
        if (old == NCTA - 1) {
            g_count = 0;
            __threadfence();
            g_flag = sense;
        } else {
            while (g_flag != sense) { }
            __threadfence();
        }
    }
    __syncthreads();
}

// ---- phase 2: persistent recurrence. 128 CTAs x 512 threads.
// CTA = (hgrp: 32 h, b-quarter: 16 b). Weights [32][1028] resident in smem.
// Activations read DIRECTLY from g_outT[t-1] (L2-resident, fresh addresses
// per step -> no staleness, no staging races). Thread: jg = tid>>6 (8-way
// j-split, 128 j each); i64 = tid&63 -> wh = i64>>5, hg = (i64>>2)&7,
// bq = i64&3; owns h {hg+16wh, hg+8+16wh} x b {bq, bq+4, bq+8, bq+12}.
// f32x2 lanes pair consecutive j -> zero-MOV inner loop, acc = 8 ull only.
extern __shared__ float rnn_smem[];
__global__ __launch_bounds__(512, 1) void rnn_kernel(const float* __restrict__ bh) {
    float* sW = rnn_smem;                                                 // [32][1028]
    unsigned long long* sRed = (unsigned long long*)(rnn_smem + 32 * WSTR); // [8][520]

    const int cta = blockIdx.x;
    const int tid = threadIdx.x;
    const int hgrp = cta >> 2;
    const int b0 = (cta & 3) * 16;
    const int jg = tid >> 6;
    const int i64 = tid & 63;
    const int wh = i64 >> 5;
    const int hg = (i64 >> 2) & 7;
    const int bq = i64 & 3;
    const int jbase = jg * 128;
    const int b_own = tid >> 5;          // 0..15
    const int h_own = tid & 31;          // 0..31
    const int hOutG = hgrp * 32 + h_own;
    const int bOut = b0 + b_own;

    {   // resident weights, once per launch
        const float4* src = (const float4*)(g_eWhP2 + (size_t)hgrp * (32 * WSTR));
        float4* dst = (float4*)sW;
        for (int i = tid; i < 32 * WSTR / 4; i += 512) dst[i] = src[i];
    }

    const float bhv = bh[hOutG];
    unsigned sense = 0;
    float st;
    {   // step 0: out_prev == 0
        float xq = g_xq[(size_t)hOutG * 64 + bOut];
        st = ALPHA * (xq + bhv);
        float ov = tanhf(fmaxf(st, 0.f));
        g_outT[(size_t)bOut * HID + hOutG] = ov;
        g_outAll[(size_t)hOutG * 64 + bOut] = ov;
    }
    grid_barrier(sense);   // barrier #1 (also orders sW staging)

    const float* wR0 = sW + (size_t)(hg + 16 * wh) * WSTR + jbase;
    const float* wR1 = sW + (size_t)(hg + 8 + 16 * wh) * WSTR + jbase;

    for (int t = 1; t < T_STEPS; t++) {
        const float* aP = g_outT + (size_t)(t - 1) * (BATCH * HID) + jbase;
        const float* a0p = aP + (size_t)(b0 + bq + 0) * HID;
        const float* a1p = aP + (size_t)(b0 + bq + 4) * HID;
        const float* a2p = aP + (size_t)(b0 + bq + 8) * HID;
        const float* a3p = aP + (size_t)(b0 + bq + 12) * HID;
        float xq = g_xq[(size_t)t * (HID * BATCH) + (size_t)hOutG * 64 + bOut];

        unsigned long long acc[2][4];
#pragma unroll
        for (int k = 0; k < 2; k++)
#pragma unroll
            for (int m = 0; m < 4; m++) acc[k][m] = 0ull;

#pragma unroll 2
        for (int q = 0; q < 32; q++) {
            int j0 = q * 4;
            ulonglong2 w0 = *(const ulonglong2*)(wR0 + j0);
            ulonglong2 w1 = *(const ulonglong2*)(wR1 + j0);
            ulonglong2 a0 = *(const ulonglong2*)(a0p + j0);
            ulonglong2 a1 = *(const ulonglong2*)(a1p + j0);
            ulonglong2 a2 = *(const ulonglong2*)(a2p + j0);
            ulonglong2 a3 = *(const ulonglong2*)(a3p + j0);
            acc[0][0] = ffma2(a0.x, w0.x, acc[0][0]); acc[0][0] = ffma2(a0.y, w0.y, acc[0][0]);
            acc[0][1] = ffma2(a1.x, w0.x, acc[0][1]); acc[0][1] = ffma2(a1.y, w0.y, acc[0][1]);
            acc[0][2] = ffma2(a2.x, w0.x, acc[0][2]); acc[0][2] = ffma2(a2.y, w0.y, acc[0][2]);
            acc[0][3] = ffma2(a3.x, w0.x, acc[0][3]); acc[0][3] = ffma2(a3.y, w0.y, acc[0][3]);
            acc[1][0] = ffma2(a0.x, w1.x, acc[1][0]); acc[1][0] = ffma2(a0.y, w1.y, acc[1][0]);
            acc[1][1] = ffma2(a1.x, w1.x, acc[1][1]); acc[1][1] = ffma2(a1.y, w1.y, acc[1][1]);
            acc[1][2] = ffma2(a2.x, w1.x, acc[1][2]); acc[1][2] = ffma2(a2.y, w1.y, acc[1][2]);
            acc[1][3] = ffma2(a3.x, w1.x, acc[1][3]); acc[1][3] = ffma2(a3.y, w1.y, acc[1][3]);
        }

        // cross-jg reduction: 8 partial ulls per output (oid = b_local*32 + h_local)
#pragma unroll
        for (int k = 0; k < 2; k++)
#pragma unroll
            for (int m = 0; m < 4; m++)
                sRed[jg * 520 + (bq + 4 * m) * 32 + (hg + 8 * k + 16 * wh)] = acc[k][m];
        __syncthreads();
        unsigned long long s = sRed[tid];          // oid_own == tid
#pragma unroll
        for (int g = 1; g < 8; g++) s = fadd2(s, sRed[g * 520 + tid]);
        float f0, f1; upk2(s, f0, f1);
        float r = f0 + f1;

        st = OMALPHA * st + ALPHA * (xq + r + bhv);
        float ov = tanhf(fmaxf(st, 0.f));
        g_outT[(size_t)t * (BATCH * HID) + (size_t)bOut * HID + hOutG] = ov;
        g_outAll[(size_t)t * (HID * BATCH) + (size_t)hOutG * 64 + bOut] = ov;

        grid_barrier(sense);   // 1000 total (even) -> flag replay-safe
    }
}

// ---- phase 3 (proven): y[t][b][o] = sum_j out[t][j][b]*eWoT[j][o]+bias
__global__ __launch_bounds__(256) void readout_kernel(const float* __restrict__ bo,
                                                      const float* __restrict__ bv,
                                                      float* __restrict__ y) {
    __shared__ float outS[64][64];
    const int t = blockIdx.x;
    const int tid = threadIdx.x;
    const int tx = tid & 15, ty = tid >> 4;
    const int b4 = tx * 4, o4 = ty * 4;
    const float* outT = g_outAll + (size_t)t * (HID * BATCH);

    unsigned long long acc[4][2];
#pragma unroll
    for (int i = 0; i < 4; i++) { acc[i][0] = 0ull; acc[i][1] = 0ull; }
    float accv[4] = {0.f, 0.f, 0.f, 0.f};

    for (int tile = 0; tile < 16; tile++) {
        __syncthreads();
#pragma unroll
        for (int k = 0; k < 4; k++) {
            int fid = tid + k * 256;
            ((float4*)&outS[0][0])[fid] = ((const float4*)(outT + (size_t)tile * 4096))[fid];
        }
        __syncthreads();
#pragma unroll 4
        for (int jj = 0; jj < 64; jj++) {
            int j = tile * 64 + jj;
            float4 ov = *(const float4*)&outS[jj][b4];
            ulonglong2 wq = __ldg((const ulonglong2*)(g_eWoT + (size_t)j * OPAD + o4));
            unsigned long long a0 = pk2(ov.x, ov.x), a1 = pk2(ov.y, ov.y);
            unsigned long long a2 = pk2(ov.z, ov.z), a3 = pk2(ov.w, ov.w);
            acc[0][0] = ffma2(a0, wq.x, acc[0][0]); acc[0][1] = ffma2(a0, wq.y, acc[0][1]);
            acc[1][0] = ffma2(a1, wq.x, acc[1][0]); acc[1][1] = ffma2(a1, wq.y, acc[1][1]);
            acc[2][0] = ffma2(a2, wq.x, acc[2][0]); acc[2][1] = ffma2(a2, wq.y, acc[2][1]);
            acc[3][0] = ffma2(a3, wq.x, acc[3][0]); acc[3][1] = ffma2(a3, wq.y, acc[3][1]);
            if (ty == 0) {
                float w64 = __ldg(g_eWoT + (size_t)j * OPAD + 64);
                accv[0] += ov.x * w64; accv[1] += ov.y * w64;
                accv[2] += ov.z * w64; accv[3] += ov.w * w64;
            }
        }
    }

    float* yt = y + (size_t)t * (BATCH * NY);
    const float bo0 = bo[o4], bo1 = bo[o4 + 1], bo2 = bo[o4 + 2], bo3 = bo[o4 + 3];
#pragma unroll
    for (int i = 0; i < 4; i++) {
        float f0, f1, f2, f3;
        upk2(acc[i][0], f0, f1);
        upk2(acc[i][1], f2, f3);
        float* yr = yt + (size_t)(b4 + i) * NY;
        yr[o4 + 0] = f0 + bo0; yr[o4 + 1] = f1 + bo1;
        yr[o4 + 2] = f2 + bo2; yr[o4 + 3] = f3 + bo3;
        if (ty == 0) yr[64] = accv[i] + bv[0];
    }
}

extern "C" void kernel_launch(void* const* d_in, const int* in_sizes, int n_in,
                              void* d_out, int out_size) {
    const float* x  = (const float*)d_in[0];
    const float* Wx = (const float*)d_in[1];
    const float* Wh = (const float*)d_in[2];
    const float* bh = (const float*)d_in[3];
    const float* Wo = (const float*)d_in[4];
    const float* bo = (const float*)d_in[5];
    const float* Wv = (const float*)d_in[6];
    const float* bv = (const float*)d_in[7];
    float* y = (float*)d_out;
    (void)in_sizes; (void)n_in; (void)out_size;

    {
        int total = HID * HID + NY * HID;
        prep_kernel<<<(total + 255) / 256, 256>>>(Wh, Wo, Wv);
    }
    xproj_kernel<<<dim3(HID / 128, T_STEPS), 256>>>(x, Wx);
    // 131584 B weights + 33280 B reduction scratch = 164864 B
    static const int RNN_SMEM = 32 * WSTR * 4 + 8 * 520 * 8;
    cudaFuncSetAttribute(rnn_kernel, cudaFuncAttributeMaxDynamicSharedMemorySize, RNN_SMEM);
    rnn_kernel<<<NCTA, 512, RNN_SMEM>>>(bh);
    readout_kernel<<<T_STEPS, 256>>>(bo, bv, y);
}

// round 11
// speedup vs baseline: 1.9813x; 1.9813x over previous
#include <cuda_runtime.h>
#include <cuda_pipeline.h>
#include <math.h>
#include <stdint.h>

#define T_STEPS 1000
#define BATCH   64
#define IN_DIM  512
#define HID     1024
#define OUT_DIM 64
#define NY      65
#define E_SZ    819
#define ALPHA   0.2f
#define OMALPHA 0.8f
#define NCTA 128
#define OPAD 80
#define WSTR 1028            // padded j-row stride (floats), 16B-aligned rows

__device__ float g_xq[(size_t)T_STEPS * HID * BATCH];     // [t][h][b]
__device__ float g_outAll[(size_t)T_STEPS * HID * BATCH]; // [t][j][b] (readout)
__device__ float g_outT[(size_t)T_STEPS * BATCH * HID];   // [t][b][j] (rnn)
__device__ float g_eWhP2[32 * 32 * WSTR];                 // [hgrp][h&31][j pad]
__device__ float g_eWoT[HID * OPAD];                      // [j][o]
__device__ unsigned g_count;
__device__ volatile unsigned g_flag;                      // 1000 flips (even) -> replay safe

__device__ __forceinline__ unsigned long long pk2(float x, float y) {
    unsigned long long r;
    asm("mov.b64 %0, {%1, %2};" : "=l"(r) : "r"(__float_as_uint(x)), "r"(__float_as_uint(y)));
    return r;
}
__device__ __forceinline__ void upk2(unsigned long long v, float &x, float &y) {
    unsigned xi, yi;
    asm("mov.b64 {%0, %1}, %2;" : "=r"(xi), "=r"(yi) : "l"(v));
    x = __uint_as_float(xi); y = __uint_as_float(yi);
}
__device__ __forceinline__ unsigned long long ffma2(unsigned long long a,
                                                    unsigned long long b,
                                                    unsigned long long c) {
    unsigned long long d;
    asm("fma.rn.f32x2 %0, %1, %2, %3;" : "=l"(d) : "l"(a), "l"(b), "l"(c));
    return d;
}
__device__ __forceinline__ unsigned long long fadd2(unsigned long long a,
                                                    unsigned long long b) {
    unsigned long long d;
    asm("add.rn.f32x2 %0, %1, %2;" : "=l"(d) : "l"(a), "l"(b));
    return d;
}

__global__ void prep_kernel(const float* __restrict__ Wh,
                            const float* __restrict__ Wo,
                            const float* __restrict__ Wv) {
    int idx = blockIdx.x * blockDim.x + threadIdx.x;
    const int N1 = HID * HID;
    if (idx < N1) {
        int h = idx >> 10, j = idx & 1023;
        float v = Wh[idx];
        v = v > 0.f ? v : 0.f;
        float s = (j < E_SZ) ? 1.f : -1.f;
        v = (h == j) ? 0.f : v * s;
        g_eWhP2[(size_t)(h >> 5) * (32 * WSTR) + (size_t)(h & 31) * WSTR + j] = v;
    } else if (idx < N1 + NY * HID) {
        int i2 = idx - N1;
        int o = i2 >> 10, j = i2 & 1023;
        float v = (o < OUT_DIM) ? Wo[o * HID + j] : Wv[j];
        v = v > 0.f ? v : 0.f;
        if (j >= E_SZ) v = 0.f;
        g_eWoT[(size_t)j * OPAD + o] = v;
    }
}

// ---- phase 1 (proven): g_xq[t][h][b] = sum_k x[t][b][k]*relu(Wx[h][k])
__global__ __launch_bounds__(256) void xproj_kernel(const float* __restrict__ x,
                                                    const float* __restrict__ Wx) {
    __shared__ float As[16][64];
    __shared__ float Bs[16][128];
    const int t  = blockIdx.y;
    const int h0 = blockIdx.x * 128;
    const int tid = threadIdx.x;
    const int tx = tid & 15;
    const int ty = tid >> 4;

    unsigned long long acc[4][4];
#pragma unroll
    for (int i = 0; i < 4; i++)
#pragma unroll
        for (int p = 0; p < 4; p++) acc[i][p] = 0ull;

    const float* xb = x + (size_t)t * BATCH * IN_DIM;
    const int bb  = tid >> 2;
    const int kk4 = (tid & 3) << 2;
    const int hh  = tid & 127;
    const int kq  = (tid >> 7) << 3;

    for (int k0 = 0; k0 < IN_DIM; k0 += 16) {
        __syncthreads();
        float4 av = *(const float4*)&xb[(size_t)bb * IN_DIM + k0 + kk4];
        As[kk4 + 0][bb] = av.x; As[kk4 + 1][bb] = av.y;
        As[kk4 + 2][bb] = av.z; As[kk4 + 3][bb] = av.w;
        const float* wrow = Wx + (size_t)(h0 + hh) * IN_DIM + k0 + kq;
        float4 w0 = *(const float4*)wrow;
        float4 w1 = *(const float4*)(wrow + 4);
        Bs[kq + 0][hh] = fmaxf(w0.x, 0.f); Bs[kq + 1][hh] = fmaxf(w0.y, 0.f);
        Bs[kq + 2][hh] = fmaxf(w0.z, 0.f); Bs[kq + 3][hh] = fmaxf(w0.w, 0.f);
        Bs[kq + 4][hh] = fmaxf(w1.x, 0.f); Bs[kq + 5][hh] = fmaxf(w1.y, 0.f);
        Bs[kq + 6][hh] = fmaxf(w1.z, 0.f); Bs[kq + 7][hh] = fmaxf(w1.w, 0.f);
        __syncthreads();
#pragma unroll
        for (int kk = 0; kk < 16; kk++) {
            float4 a = *(const float4*)&As[kk][tx << 2];
            ulonglong2 wA = *(const ulonglong2*)&Bs[kk][(ty << 3)];
            ulonglong2 wB = *(const ulonglong2*)&Bs[kk][(ty << 3) + 4];
            unsigned long long a0 = pk2(a.x, a.x), a1 = pk2(a.y, a.y);
            unsigned long long a2 = pk2(a.z, a.z), a3 = pk2(a.w, a.w);
            acc[0][0] = ffma2(a0, wA.x, acc[0][0]); acc[0][1] = ffma2(a0, wA.y, acc[0][1]);
            acc[0][2] = ffma2(a0, wB.x, acc[0][2]); acc[0][3] = ffma2(a0, wB.y, acc[0][3]);
            acc[1][0] = ffma2(a1, wA.x, acc[1][0]); acc[1][1] = ffma2(a1, wA.y, acc[1][1]);
            acc[1][2] = ffma2(a1, wB.x, acc[1][2]); acc[1][3] = ffma2(a1, wB.y, acc[1][3]);
            acc[2][0] = ffma2(a2, wA.x, acc[2][0]); acc[2][1] = ffma2(a2, wA.y, acc[2][1]);
            acc[2][2] = ffma2(a2, wB.x, acc[2][2]); acc[2][3] = ffma2(a2, wB.y, acc[2][3]);
            acc[3][0] = ffma2(a3, wA.x, acc[3][0]); acc[3][1] = ffma2(a3, wA.y, acc[3][1]);
            acc[3][2] = ffma2(a3, wB.x, acc[3][2]); acc[3][3] = ffma2(a3, wB.y, acc[3][3]);
        }
    }
    float* xqo = g_xq + (size_t)t * (HID * BATCH);
#pragma unroll
    for (int i = 0; i < 4; i++) {
        int b = (tx << 2) + i;
#pragma unroll
        for (int p = 0; p < 4; p++) {
            float f0, f1; upk2(acc[i][p], f0, f1);
            int h = h0 + (ty << 3) + (p << 1);
            xqo[(size_t)h * 64 + b]       = f0;
            xqo[(size_t)(h + 1) * 64 + b] = f1;
        }
    }
}

__device__ __forceinline__ void grid_barrier(unsigned &sense) {
    sense ^= 1u;
    __threadfence();
    __syncthreads();
    if (threadIdx.x == 0) {
        unsigned old = atomicAdd(&g_count, 1u);
        if (old == NCTA - 1) {
            g_count = 0;
            __threadfence();
            g_flag = sense;
        } else {
            while (g_flag != sense) { }
            __threadfence();
        }
    }
    __syncthreads();
}

// ---- phase 2: persistent recurrence. 128 CTAs x 256 threads.
// CTA = (hgrp: 32 h, b-quarter: 16 b). Weights [32][1028] resident in smem
// for all 1000 steps. Activation slice (16b x 1024j, 64 KB) staged per step
// via ONE cp.async group (16 chunks/thread, single commit/wait/syncthreads
// -> no multi-group ordering races). Thread: jg = tid>>6 (4-way j split,
// 256 j each); i64 = tid&63 -> wh = i64>>5, hg = (i64>>2)&7, bq = i64&3;
// in-loop owns h {hg+16wh, hg+8+16wh} x b {bq,+4,+8,+12}. f32x2 lanes pair
// consecutive j -> zero-MOV inner loop. Final: thread owns outputs
// oid = tid and tid+256 (oid = b_local*32 + h_local).
extern __shared__ float rnn_smem[];
__global__ __launch_bounds__(256, 1) void rnn_kernel(const float* __restrict__ bh) {
    float* sW = rnn_smem;                                   // [32][1028]
    float* sA = rnn_smem + 32 * WSTR;                       // [16][1028]
    unsigned long long* sRed =
        (unsigned long long*)(rnn_smem + 48 * WSTR);        // [4][520]

    const int cta = blockIdx.x;
    const int tid = threadIdx.x;
    const int hgrp = cta >> 2;
    const int b0 = (cta & 3) * 16;
    const int jg = tid >> 6;
    const int i64 = tid & 63;
    const int wh = i64 >> 5;
    const int hg = (i64 >> 2) & 7;
    const int bq = i64 & 3;
    const int jbase = jg * 256;
    // final outputs: oid = tid (+256)
    const int h_own = tid & 31;
    const int bl0 = tid >> 5;            // 0..7
    const int hOutG = hgrp * 32 + h_own;
    const int bOut0 = b0 + bl0;
    const int bOut1 = b0 + bl0 + 8;
    // staging: row = tid>>4, 16 chunks of 16B at (tid&15)*4 + 64*k floats
    const int srow = tid >> 4;
    const int scol = (tid & 15) * 4;

    {   // resident weights, once per launch
        const float4* src = (const float4*)(g_eWhP2 + (size_t)hgrp * (32 * WSTR));
        float4* dst = (float4*)sW;
        for (int i = tid; i < 32 * WSTR / 4; i += 256) dst[i] = src[i];
    }

    const float bhv = bh[hOutG];
    unsigned sense = 0;
    float st0, st1;
    {   // step 0: out_prev == 0
        float xqA = g_xq[(size_t)hOutG * 64 + bOut0];
        float xqB = g_xq[(size_t)hOutG * 64 + bOut1];
        st0 = ALPHA * (xqA + bhv);
        st1 = ALPHA * (xqB + bhv);
        float ovA = tanhf(fmaxf(st0, 0.f));
        float ovB = tanhf(fmaxf(st1, 0.f));
        g_outT[(size_t)bOut0 * HID + hOutG] = ovA;
        g_outT[(size_t)bOut1 * HID + hOutG] = ovB;
        g_outAll[(size_t)hOutG * 64 + bOut0] = ovA;
        g_outAll[(size_t)hOutG * 64 + bOut1] = ovB;
    }
    grid_barrier(sense);   // barrier #1 (also orders sW staging)

    const float* wR0 = sW + (size_t)(hg + 16 * wh) * WSTR + jbase;
    const float* wR1 = sW + (size_t)(hg + 8 + 16 * wh) * WSTR + jbase;
    const float* aR0 = sA + (size_t)(bq + 0) * WSTR + jbase;
    const float* aR1 = sA + (size_t)(bq + 4) * WSTR + jbase;
    const float* aR2 = sA + (size_t)(bq + 8) * WSTR + jbase;
    const float* aR3 = sA + (size_t)(bq + 12) * WSTR + jbase;

    for (int t = 1; t < T_STEPS; t++) {
        // stage whole 16b x 1024j slice, ONE group
        {
            const float* srcRow = g_outT + (size_t)(t - 1) * (BATCH * HID)
                                + (size_t)(b0 + srow) * HID + scol;
            float* dstRow = sA + (size_t)srow * WSTR + scol;
#pragma unroll
            for (int k = 0; k < 16; k++)
                __pipeline_memcpy_async(dstRow + k * 64, srcRow + k * 64, 16);
            __pipeline_commit();
        }
        float xqA = g_xq[(size_t)t * (HID * BATCH) + (size_t)hOutG * 64 + bOut0];
        float xqB = g_xq[(size_t)t * (HID * BATCH) + (size_t)hOutG * 64 + bOut1];

        unsigned long long acc[2][4];
#pragma unroll
        for (int k = 0; k < 2; k++)
#pragma unroll
            for (int m = 0; m < 4; m++) acc[k][m] = 0ull;

        __pipeline_wait_prior(0);
        __syncthreads();            // whole slice visible to all threads

#pragma unroll 4
        for (int q = 0; q < 64; q++) {
            int j0 = q * 4;
            ulonglong2 w0 = *(const ulonglong2*)(wR0 + j0);
            ulonglong2 w1 = *(const ulonglong2*)(wR1 + j0);
            ulonglong2 a0 = *(const ulonglong2*)(aR0 + j0);
            ulonglong2 a1 = *(const ulonglong2*)(aR1 + j0);
            ulonglong2 a2 = *(const ulonglong2*)(aR2 + j0);
            ulonglong2 a3 = *(const ulonglong2*)(aR3 + j0);
            acc[0][0] = ffma2(a0.x, w0.x, acc[0][0]); acc[0][0] = ffma2(a0.y, w0.y, acc[0][0]);
            acc[0][1] = ffma2(a1.x, w0.x, acc[0][1]); acc[0][1] = ffma2(a1.y, w0.y, acc[0][1]);
            acc[0][2] = ffma2(a2.x, w0.x, acc[0][2]); acc[0][2] = ffma2(a2.y, w0.y, acc[0][2]);
            acc[0][3] = ffma2(a3.x, w0.x, acc[0][3]); acc[0][3] = ffma2(a3.y, w0.y, acc[0][3]);
            acc[1][0] = ffma2(a0.x, w1.x, acc[1][0]); acc[1][0] = ffma2(a0.y, w1.y, acc[1][0]);
            acc[1][1] = ffma2(a1.x, w1.x, acc[1][1]); acc[1][1] = ffma2(a1.y, w1.y, acc[1][1]);
            acc[1][2] = ffma2(a2.x, w1.x, acc[1][2]); acc[1][2] = ffma2(a2.y, w1.y, acc[1][2]);
            acc[1][3] = ffma2(a3.x, w1.x, acc[1][3]); acc[1][3] = ffma2(a3.y, w1.y, acc[1][3]);
        }

        // cross-jg reduction: 4 partial ulls per output (oid = b_local*32 + h_local)
#pragma unroll
        for (int k = 0; k < 2; k++)
#pragma unroll
            for (int m = 0; m < 4; m++)
                sRed[jg * 520 + (bq + 4 * m) * 32 + (hg + 8 * k + 16 * wh)] = acc[k][m];
        __syncthreads();
        unsigned long long sA_ = sRed[tid];
        unsigned long long sB_ = sRed[tid + 256];
#pragma unroll
        for (int g = 1; g < 4; g++) {
            sA_ = fadd2(sA_, sRed[g * 520 + tid]);
            sB_ = fadd2(sB_, sRed[g * 520 + tid + 256]);
        }
        float fa0, fa1, fb0, fb1;
        upk2(sA_, fa0, fa1);
        upk2(sB_, fb0, fb1);
        float rA = fa0 + fa1, rB = fb0 + fb1;

        st0 = OMALPHA * st0 + ALPHA * (xqA + rA + bhv);
        st1 = OMALPHA * st1 + ALPHA * (xqB + rB + bhv);
        float ovA = tanhf(fmaxf(st0, 0.f));
        float ovB = tanhf(fmaxf(st1, 0.f));
        g_outT[(size_t)t * (BATCH * HID) + (size_t)bOut0 * HID + hOutG] = ovA;
        g_outT[(size_t)t * (BATCH * HID) + (size_t)bOut1 * HID + hOutG] = ovB;
        g_outAll[(size_t)t * (HID * BATCH) + (size_t)hOutG * 64 + bOut0] = ovA;
        g_outAll[(size_t)t * (HID * BATCH) + (size_t)hOutG * 64 + bOut1] = ovB;

        grid_barrier(sense);   // 1000 total (even) -> flag replay-safe
    }
}

// ---- phase 3 (proven): y[t][b][o] = sum_j out[t][j][b]*eWoT[j][o]+bias
__global__ __launch_bounds__(256) void readout_kernel(const float* __restrict__ bo,
                                                      const float* __restrict__ bv,
                                                      float* __restrict__ y) {
    __shared__ float outS[64][64];
    const int t = blockIdx.x;
    const int tid = threadIdx.x;
    const int tx = tid & 15, ty = tid >> 4;
    const int b4 = tx * 4, o4 = ty * 4;
    const float* outT = g_outAll + (size_t)t * (HID * BATCH);

    unsigned long long acc[4][2];
#pragma unroll
    for (int i = 0; i < 4; i++) { acc[i][0] = 0ull; acc[i][1] = 0ull; }
    float accv[4] = {0.f, 0.f, 0.f, 0.f};

    for (int tile = 0; tile < 16; tile++) {
        __syncthreads();
#pragma unroll
        for (int k = 0; k < 4; k++) {
            int fid = tid + k * 256;
            ((float4*)&outS[0][0])[fid] = ((const float4*)(outT + (size_t)tile * 4096))[fid];
        }
        __syncthreads();
#pragma unroll 4
        for (int jj = 0; jj < 64; jj++) {
            int j = tile * 64 + jj;
            float4 ov = *(const float4*)&outS[jj][b4];
            ulonglong2 wq = __ldg((const ulonglong2*)(g_eWoT + (size_t)j * OPAD + o4));
            unsigned long long a0 = pk2(ov.x, ov.x), a1 = pk2(ov.y, ov.y);
            unsigned long long a2 = pk2(ov.z, ov.z), a3 = pk2(ov.w, ov.w);
            acc[0][0] = ffma2(a0, wq.x, acc[0][0]); acc[0][1] = ffma2(a0, wq.y, acc[0][1]);
            acc[1][0] = ffma2(a1, wq.x, acc[1][0]); acc[1][1] = ffma2(a1, wq.y, acc[1][1]);
            acc[2][0] = ffma2(a2, wq.x, acc[2][0]); acc[2][1] = ffma2(a2, wq.y, acc[2][1]);
            acc[3][0] = ffma2(a3, wq.x, acc[3][0]); acc[3][1] = ffma2(a3, wq.y, acc[3][1]);
            if (ty == 0) {
                float w64 = __ldg(g_eWoT + (size_t)j * OPAD + 64);
                accv[0] += ov.x * w64; accv[1] += ov.y * w64;
                accv[2] += ov.z * w64; accv[3] += ov.w * w64;
            }
        }
    }

    float* yt = y + (size_t)t * (BATCH * NY);
    const float bo0 = bo[o4], bo1 = bo[o4 + 1], bo2 = bo[o4 + 2], bo3 = bo[o4 + 3];
#pragma unroll
    for (int i = 0; i < 4; i++) {
        float f0, f1, f2, f3;
        upk2(acc[i][0], f0, f1);
        upk2(acc[i][1], f2, f3);
        float* yr = yt + (size_t)(b4 + i) * NY;
        yr[o4 + 0] = f0 + bo0; yr[o4 + 1] = f1 + bo1;
        yr[o4 + 2] = f2 + bo2; yr[o4 + 3] = f3 + bo3;
        if (ty == 0) yr[64] = accv[i] + bv[0];
    }
}

extern "C" void kernel_launch(void* const* d_in, const int* in_sizes, int n_in,
                              void* d_out, int out_size) {
    const float* x  = (const float*)d_in[0];
    const float* Wx = (const float*)d_in[1];
    const float* Wh = (const float*)d_in[2];
    const float* bh = (const float*)d_in[3];
    const float* Wo = (const float*)d_in[4];
    const float* bo = (const float*)d_in[5];
    const float* Wv = (const float*)d_in[6];
    const float* bv = (const float*)d_in[7];
    float* y = (float*)d_out;
    (void)in_sizes; (void)n_in; (void)out_size;

    {
        int total = HID * HID + NY * HID;
        prep_kernel<<<(total + 255) / 256, 256>>>(Wh, Wo, Wv);
    }
    xproj_kernel<<<dim3(HID / 128, T_STEPS), 256>>>(x, Wx);
    // 128K weights + 64.25K acts + 16.25K reduce = 214016 B
    static const int RNN_SMEM = 48 * WSTR * 4 + 4 * 520 * 8;
    cudaFuncSetAttribute(rnn_kernel, cudaFuncAttributeMaxDynamicSharedMemorySize, RNN_SMEM);
    rnn_kernel<<<NCTA, 256, RNN_SMEM>>>(bh);
    readout_kernel<<<T_STEPS, 256>>>(bo, bv, y);
}

// round 12
// speedup vs baseline: 2.0316x; 1.0254x over previous
#include <cuda_runtime.h>
#include <cuda_pipeline.h>
#include <math.h>
#include <stdint.h>

#define T_STEPS 1000
#define BATCH   64
#define IN_DIM  512
#define HID     1024
#define OUT_DIM 64
#define NY      65
#define E_SZ    819
#define ALPHA   0.2f
#define OMALPHA 0.8f
#define NCTA 128
#define OPAD 80
#define WSTR 1028            // padded j-row stride (floats), 16B-aligned rows

__device__ float g_xq[(size_t)T_STEPS * BATCH * HID];     // [t][b][h]  (coalesced for rnn)
__device__ float g_outAll[(size_t)T_STEPS * HID * BATCH]; // [t][j][b]  (readout)
__device__ float g_outT[(size_t)T_STEPS * BATCH * HID];   // [t][b][j]  (rnn broadcast)
__device__ float g_eWhP2[32 * 32 * WSTR];                 // [hgrp][h&31][j pad]
__device__ float g_eWoT[HID * OPAD];                      // [j][o]
__device__ unsigned g_count;
__device__ volatile unsigned g_flag;                      // 1000 flips (even) -> replay safe

__device__ __forceinline__ unsigned long long pk2(float x, float y) {
    unsigned long long r;
    asm("mov.b64 %0, {%1, %2};" : "=l"(r) : "r"(__float_as_uint(x)), "r"(__float_as_uint(y)));
    return r;
}
__device__ __forceinline__ void upk2(unsigned long long v, float &x, float &y) {
    unsigned xi, yi;
    asm("mov.b64 {%0, %1}, %2;" : "=r"(xi), "=r"(yi) : "l"(v));
    x = __uint_as_float(xi); y = __uint_as_float(yi);
}
__device__ __forceinline__ unsigned long long ffma2(unsigned long long a,
                                                    unsigned long long b,
                                                    unsigned long long c) {
    unsigned long long d;
    asm("fma.rn.f32x2 %0, %1, %2, %3;" : "=l"(d) : "l"(a), "l"(b), "l"(c));
    return d;
}
__device__ __forceinline__ unsigned long long fadd2(unsigned long long a,
                                                    unsigned long long b) {
    unsigned long long d;
    asm("add.rn.f32x2 %0, %1, %2;" : "=l"(d) : "l"(a), "l"(b));
    return d;
}

__global__ void noop_kernel() {}

__global__ void prep_kernel(const float* __restrict__ Wh,
                            const float* __restrict__ Wo,
                            const float* __restrict__ Wv) {
    int idx = blockIdx.x * blockDim.x + threadIdx.x;
    const int N1 = HID * HID;
    if (idx < N1) {
        int h = idx >> 10, j = idx & 1023;
        float v = Wh[idx];
        v = v > 0.f ? v : 0.f;
        float s = (j < E_SZ) ? 1.f : -1.f;
        v = (h == j) ? 0.f : v * s;
        g_eWhP2[(size_t)(h >> 5) * (32 * WSTR) + (size_t)(h & 31) * WSTR + j] = v;
    } else if (idx < N1 + NY * HID) {
        int i2 = idx - N1;
        int o = i2 >> 10, j = i2 & 1023;
        float v = (o < OUT_DIM) ? Wo[o * HID + j] : Wv[j];
        v = v > 0.f ? v : 0.f;
        if (j >= E_SZ) v = 0.f;
        g_eWoT[(size_t)j * OPAD + o] = v;
    }
}

// ---- phase 1: g_xq[t][b][h] = sum_k x[t][b][k]*relu(Wx[h][k])
__global__ __launch_bounds__(256) void xproj_kernel(const float* __restrict__ x,
                                                    const float* __restrict__ Wx) {
    __shared__ float As[16][64];
    __shared__ float Bs[16][128];
    const int t  = blockIdx.y;
    const int h0 = blockIdx.x * 128;
    const int tid = threadIdx.x;
    const int tx = tid & 15;
    const int ty = tid >> 4;

    unsigned long long acc[4][4];
#pragma unroll
    for (int i = 0; i < 4; i++)
#pragma unroll
        for (int p = 0; p < 4; p++) acc[i][p] = 0ull;

    const float* xb = x + (size_t)t * BATCH * IN_DIM;
    const int bb  = tid >> 2;
    const int kk4 = (tid & 3) << 2;
    const int hh  = tid & 127;
    const int kq  = (tid >> 7) << 3;

    for (int k0 = 0; k0 < IN_DIM; k0 += 16) {
        __syncthreads();
        float4 av = *(const float4*)&xb[(size_t)bb * IN_DIM + k0 + kk4];
        As[kk4 + 0][bb] = av.x; As[kk4 + 1][bb] = av.y;
        As[kk4 + 2][bb] = av.z; As[kk4 + 3][bb] = av.w;
        const float* wrow = Wx + (size_t)(h0 + hh) * IN_DIM + k0 + kq;
        float4 w0 = *(const float4*)wrow;
        float4 w1 = *(const float4*)(wrow + 4);
        Bs[kq + 0][hh] = fmaxf(w0.x, 0.f); Bs[kq + 1][hh] = fmaxf(w0.y, 0.f);
        Bs[kq + 2][hh] = fmaxf(w0.z, 0.f); Bs[kq + 3][hh] = fmaxf(w0.w, 0.f);
        Bs[kq + 4][hh] = fmaxf(w1.x, 0.f); Bs[kq + 5][hh] = fmaxf(w1.y, 0.f);
        Bs[kq + 6][hh] = fmaxf(w1.z, 0.f); Bs[kq + 7][hh] = fmaxf(w1.w, 0.f);
        __syncthreads();
#pragma unroll
        for (int kk = 0; kk < 16; kk++) {
            float4 a = *(const float4*)&As[kk][tx << 2];
            ulonglong2 wA = *(const ulonglong2*)&Bs[kk][(ty << 3)];
            ulonglong2 wB = *(const ulonglong2*)&Bs[kk][(ty << 3) + 4];
            unsigned long long a0 = pk2(a.x, a.x), a1 = pk2(a.y, a.y);
            unsigned long long a2 = pk2(a.z, a.z), a3 = pk2(a.w, a.w);
            acc[0][0] = ffma2(a0, wA.x, acc[0][0]); acc[0][1] = ffma2(a0, wA.y, acc[0][1]);
            acc[0][2] = ffma2(a0, wB.x, acc[0][2]); acc[0][3] = ffma2(a0, wB.y, acc[0][3]);
            acc[1][0] = ffma2(a1, wA.x, acc[1][0]); acc[1][1] = ffma2(a1, wA.y, acc[1][1]);
            acc[1][2] = ffma2(a1, wB.x, acc[1][2]); acc[1][3] = ffma2(a1, wB.y, acc[1][3]);
            acc[2][0] = ffma2(a2, wA.x, acc[2][0]); acc[2][1] = ffma2(a2, wA.y, acc[2][1]);
            acc[2][2] = ffma2(a2, wB.x, acc[2][2]); acc[2][3] = ffma2(a2, wB.y, acc[2][3]);
            acc[3][0] = ffma2(a3, wA.x, acc[3][0]); acc[3][1] = ffma2(a3, wA.y, acc[3][1]);
            acc[3][2] = ffma2(a3, wB.x, acc[3][2]); acc[3][3] = ffma2(a3, wB.y, acc[3][3]);
        }
    }
    float* xqT = g_xq + (size_t)t * (BATCH * HID);
#pragma unroll
    for (int i = 0; i < 4; i++) {
        int b = (tx << 2) + i;
#pragma unroll
        for (int p = 0; p < 4; p++) {
            float f0, f1; upk2(acc[i][p], f0, f1);
            int h = h0 + (ty << 3) + (p << 1);
            float2 v2 = make_float2(f0, f1);
            *(float2*)&xqT[(size_t)b * HID + h] = v2;   // h even -> 8B aligned
        }
    }
}

__device__ __forceinline__ void grid_barrier(unsigned &sense) {
    sense ^= 1u;
    __threadfence();
    __syncthreads();
    if (threadIdx.x == 0) {
        unsigned old = atomicAdd(&g_count, 1u);
        if (old == NCTA - 1) {
            g_count = 0;
            __threadfence();
            g_flag = sense;
        } else {
            while (g_flag != sense) { }
            __threadfence();
        }
    }
    __syncthreads();
}

// ---- phase 2: persistent recurrence. 128 CTAs x 512 threads (4 warps/SMSP).
// CTA = (hgrp: 32 h, b-quarter: 16 b). Weights [32][1028] resident in smem.
// Activation slice (16b x 1024j) staged per step as TWO cp.async groups
// (j<512 / j>=512); each warp computes its lower-64 j after group A and its
// upper-64 j after group B, so the group split exactly matches the j-ranges
// consumed (no R9-style races). Thread: jg = tid>>6 (8 groups); i64 = tid&63:
// wh = i64>>5, hg = (i64>>2)&7, bq = i64&3 -> in-loop owns
// h {hg+16wh, hg+8+16wh} x b {bq,+4,+8,+12}. f32x2 lanes pair consecutive j
// (zero-MOV). Final output: oid = tid = b_local*32 + h_local (one per thread).
// g_outAll store is bounced through a smem transpose (aliases dead sA).
extern __shared__ float rnn_smem[];
__global__ __launch_bounds__(512, 1) void rnn_kernel(const float* __restrict__ bh) {
    float* sW = rnn_smem;                                   // [32][1028]
    float* sA = rnn_smem + 32 * WSTR;                       // [16][1028]
    unsigned long long* sRed =
        (unsigned long long*)(rnn_smem + 48 * WSTR);        // [8][512]
    float* sOv = sA;                                        // [32][17] (aliases dead sA)

    const int cta = blockIdx.x;
    const int tid = threadIdx.x;
    const int hgrp = cta >> 2;
    const int b0 = (cta & 3) * 16;
    const int jg = tid >> 6;             // 0..7
    const int i64 = tid & 63;
    const int wh = i64 >> 5;
    const int hg = (i64 >> 2) & 7;
    const int bq = i64 & 3;
    // final output ownership: oid = tid
    const int h_own = tid & 31;
    const int b_own = tid >> 5;          // 0..15
    const int hOutG = hgrp * 32 + h_own;
    const int bOut = b0 + b_own;
    // outAll bounce reader mapping
    const int h_s = tid >> 4;            // 0..31
    const int b_s = tid & 15;
    // staging: srow = tid>>5 (0..15); chunk j = (tid&31)*4 + k*128
    const int srow = tid >> 5;
    const int scol = (tid & 31) * 4;

    {   // resident weights, once per launch
        const float4* src = (const float4*)(g_eWhP2 + (size_t)hgrp * (32 * WSTR));
        float4* dst = (float4*)sW;
        for (int i = tid; i < 32 * WSTR / 4; i += 512) dst[i] = src[i];
    }

    const float bhv = bh[hOutG];
    unsigned sense = 0;
    float st;
    {   // step 0: out_prev == 0
        float xq = g_xq[(size_t)bOut * HID + hOutG];
        st = ALPHA * (xq + bhv);
        float ov = tanhf(fmaxf(st, 0.f));
        g_outT[(size_t)bOut * HID + hOutG] = ov;
        g_outAll[(size_t)hOutG * 64 + bOut] = ov;  // scattered once, negligible
    }
    grid_barrier(sense);   // barrier #1 (also orders sW staging)

    const float* wR0 = sW + (size_t)(hg + 16 * wh) * WSTR;
    const float* wR1 = sW + (size_t)(hg + 8 + 16 * wh) * WSTR;
    const float* aR0 = sA + (size_t)(bq + 0) * WSTR;
    const float* aR1 = sA + (size_t)(bq + 4) * WSTR;
    const float* aR2 = sA + (size_t)(bq + 8) * WSTR;
    const float* aR3 = sA + (size_t)(bq + 12) * WSTR;
    const int jlo = jg * 64;             // lower-half range [jlo, jlo+64)
    const int jhi = 512 + jg * 64;       // upper-half range

    for (int t = 1; t < T_STEPS; t++) {
        // stage group A (j < 512) then group B (j >= 512)
        {
            const float* srcRow = g_outT + (size_t)(t - 1) * (BATCH * HID)
                                + (size_t)(b0 + srow) * HID + scol;
            float* dstRow = sA + (size_t)srow * WSTR + scol;
#pragma unroll
            for (int k = 0; k < 4; k++)
                __pipeline_memcpy_async(dstRow + k * 128, srcRow + k * 128, 16);
            __pipeline_commit();
#pragma unroll
            for (int k = 4; k < 8; k++)
                __pipeline_memcpy_async(dstRow + k * 128, srcRow + k * 128, 16);
            __pipeline_commit();
        }
        float xq = g_xq[(size_t)t * (BATCH * HID) + (size_t)bOut * HID + hOutG];

        unsigned long long acc[2][4];
#pragma unroll
        for (int k = 0; k < 2; k++)
#pragma unroll
            for (int m = 0; m < 4; m++) acc[k][m] = 0ull;

        __pipeline_wait_prior(1);   // group A done (this thread)
        __syncthreads();            // -> group A visible block-wide
#pragma unroll 1
        for (int q = 0; q < 16; q++) {
            int j0 = jlo + q * 4;
            ulonglong2 w0 = *(const ulonglong2*)(wR0 + j0);
            ulonglong2 w1 = *(const ulonglong2*)(wR1 + j0);
            ulonglong2 a0 = *(const ulonglong2*)(aR0 + j0);
            ulonglong2 a1 = *(const ulonglong2*)(aR1 + j0);
            ulonglong2 a2 = *(const ulonglong2*)(aR2 + j0);
            ulonglong2 a3 = *(const ulonglong2*)(aR3 + j0);
            acc[0][0] = ffma2(a0.x, w0.x, acc[0][0]); acc[0][0] = ffma2(a0.y, w0.y, acc[0][0]);
            acc[0][1] = ffma2(a1.x, w0.x, acc[0][1]); acc[0][1] = ffma2(a1.y, w0.y, acc[0][1]);
            acc[0][2] = ffma2(a2.x, w0.x, acc[0][2]); acc[0][2] = ffma2(a2.y, w0.y, acc[0][2]);
            acc[0][3] = ffma2(a3.x, w0.x, acc[0][3]); acc[0][3] = ffma2(a3.y, w0.y, acc[0][3]);
            acc[1][0] = ffma2(a0.x, w1.x, acc[1][0]); acc[1][0] = ffma2(a0.y, w1.y, acc[1][0]);
            acc[1][1] = ffma2(a1.x, w1.x, acc[1][1]); acc[1][1] = ffma2(a1.y, w1.y, acc[1][1]);
            acc[1][2] = ffma2(a2.x, w1.x, acc[1][2]); acc[1][2] = ffma2(a2.y, w1.y, acc[1][2]);
            acc[1][3] = ffma2(a3.x, w1.x, acc[1][3]); acc[1][3] = ffma2(a3.y, w1.y, acc[1][3]);
        }
        __pipeline_wait_prior(0);   // group B done
        __syncthreads();
#pragma unroll 1
        for (int q = 0; q < 16; q++) {
            int j0 = jhi + q * 4;
            ulonglong2 w0 = *(const ulonglong2*)(wR0 + j0);
            ulonglong2 w1 = *(const ulonglong2*)(wR1 + j0);
            ulonglong2 a0 = *(const ulonglong2*)(aR0 + j0);
            ulonglong2 a1 = *(const ulonglong2*)(aR1 + j0);
            ulonglong2 a2 = *(const ulonglong2*)(aR2 + j0);
            ulonglong2 a3 = *(const ulonglong2*)(aR3 + j0);
            acc[0][0] = ffma2(a0.x, w0.x, acc[0][0]); acc[0][0] = ffma2(a0.y, w0.y, acc[0][0]);
            acc[0][1] = ffma2(a1.x, w0.x, acc[0][1]); acc[0][1] = ffma2(a1.y, w0.y, acc[0][1]);
            acc[0][2] = ffma2(a2.x, w0.x, acc[0][2]); acc[0][2] = ffma2(a2.y, w0.y, acc[0][2]);
            acc[0][3] = ffma2(a3.x, w0.x, acc[0][3]); acc[0][3] = ffma2(a3.y, w0.y, acc[0][3]);
            acc[1][0] = ffma2(a0.x, w1.x, acc[1][0]); acc[1][0] = ffma2(a0.y, w1.y, acc[1][0]);
            acc[1][1] = ffma2(a1.x, w1.x, acc[1][1]); acc[1][1] = ffma2(a1.y, w1.y, acc[1][1]);
            acc[1][2] = ffma2(a2.x, w1.x, acc[1][2]); acc[1][2] = ffma2(a2.y, w1.y, acc[1][2]);
            acc[1][3] = ffma2(a3.x, w1.x, acc[1][3]); acc[1][3] = ffma2(a3.y, w1.y, acc[1][3]);
        }

        // cross-jg reduction: 8 partial ulls per output; oid = b_local*32 + h_local
#pragma unroll
        for (int k = 0; k < 2; k++)
#pragma unroll
            for (int m = 0; m < 4; m++)
                sRed[jg * 512 + (bq + 4 * m) * 32 + (hg + 8 * k + 16 * wh)] = acc[k][m];
        __syncthreads();            // sRed ready; sA now dead -> sOv may be written below
        unsigned long long s = sRed[tid];
#pragma unroll
        for (int g = 1; g < 8; g++) s = fadd2(s, sRed[g * 512 + tid]);
        float f0, f1; upk2(s, f0, f1);
        float r = f0 + f1;

        st = OMALPHA * st + ALPHA * (xq + r + bhv);
        float ov = tanhf(fmaxf(st, 0.f));
        g_outT[(size_t)t * (BATCH * HID) + (size_t)bOut * HID + hOutG] = ov;  // coalesced
        sOv[h_own * 17 + b_own] = ov;                                        // bounce
        __syncthreads();
        g_outAll[(size_t)t * (HID * BATCH) + (size_t)(hgrp * 32 + h_s) * 64 + b0 + b_s]
            = sOv[h_s * 17 + b_s];                                           // coalesced

        grid_barrier(sense);   // 1000 total (even) -> flag replay-safe
    }
}

// ---- phase 3 (proven): y[t][b][o] = sum_j out[t][j][b]*eWoT[j][o]+bias
__global__ __launch_bounds__(256) void readout_kernel(const float* __restrict__ bo,
                                                      const float* __restrict__ bv,
                                                      float* __restrict__ y) {
    __shared__ float outS[64][64];
    const int t = blockIdx.x;
    const int tid = threadIdx.x;
    const int tx = tid & 15, ty = tid >> 4;
    const int b4 = tx * 4, o4 = ty * 4;
    const float* outT = g_outAll + (size_t)t * (HID * BATCH);

    unsigned long long acc[4][2];
#pragma unroll
    for (int i = 0; i < 4; i++) { acc[i][0] = 0ull; acc[i][1] = 0ull; }
    float accv[4] = {0.f, 0.f, 0.f, 0.f};

    for (int tile = 0; tile < 16; tile++) {
        __syncthreads();
#pragma unroll
        for (int k = 0; k < 4; k++) {
            int fid = tid + k * 256;
            ((float4*)&outS[0][0])[fid] = ((const float4*)(outT + (size_t)tile * 4096))[fid];
        }
        __syncthreads();
#pragma unroll 4
        for (int jj = 0; jj < 64; jj++) {
            int j = tile * 64 + jj;
            float4 ov = *(const float4*)&outS[jj][b4];
            ulonglong2 wq = __ldg((const ulonglong2*)(g_eWoT + (size_t)j * OPAD + o4));
            unsigned long long a0 = pk2(ov.x, ov.x), a1 = pk2(ov.y, ov.y);
            unsigned long long a2 = pk2(ov.z, ov.z), a3 = pk2(ov.w, ov.w);
            acc[0][0] = ffma2(a0, wq.x, acc[0][0]); acc[0][1] = ffma2(a0, wq.y, acc[0][1]);
            acc[1][0] = ffma2(a1, wq.x, acc[1][0]); acc[1][1] = ffma2(a1, wq.y, acc[1][1]);
            acc[2][0] = ffma2(a2, wq.x, acc[2][0]); acc[2][1] = ffma2(a2, wq.y, acc[2][1]);
            acc[3][0] = ffma2(a3, wq.x, acc[3][0]); acc[3][1] = ffma2(a3, wq.y, acc[3][1]);
            if (ty == 0) {
                float w64 = __ldg(g_eWoT + (size_t)j * OPAD + 64);
                accv[0] += ov.x * w64; accv[1] += ov.y * w64;
                accv[2] += ov.z * w64; accv[3] += ov.w * w64;
            }
        }
    }

    float* yt = y + (size_t)t * (BATCH * NY);
    const float bo0 = bo[o4], bo1 = bo[o4 + 1], bo2 = bo[o4 + 2], bo3 = bo[o4 + 3];
#pragma unroll
    for (int i = 0; i < 4; i++) {
        float f0, f1, f2, f3;
        upk2(acc[i][0], f0, f1);
        upk2(acc[i][1], f2, f3);
        float* yr = yt + (size_t)(b4 + i) * NY;
        yr[o4 + 0] = f0 + bo0; yr[o4 + 1] = f1 + bo1;
        yr[o4 + 2] = f2 + bo2; yr[o4 + 3] = f3 + bo3;
        if (ty == 0) yr[64] = accv[i] + bv[0];
    }
}

extern "C" void kernel_launch(void* const* d_in, const int* in_sizes, int n_in,
                              void* d_out, int out_size) {
    const float* x  = (const float*)d_in[0];
    const float* Wx = (const float*)d_in[1];
    const float* Wh = (const float*)d_in[2];
    const float* bh = (const float*)d_in[3];
    const float* Wo = (const float*)d_in[4];
    const float* bo = (const float*)d_in[5];
    const float* Wv = (const float*)d_in[6];
    const float* bv = (const float*)d_in[7];
    float* y = (float*)d_out;
    (void)in_sizes; (void)n_in; (void)out_size;

    {
        int total = HID * HID + NY * HID;
        prep_kernel<<<(total + 255) / 256, 256>>>(Wh, Wo, Wv);
    }
    xproj_kernel<<<dim3(HID / 128, T_STEPS), 256>>>(x, Wx);
    // align rnn_kernel into ncu's profiled slot (-s 5 -c 1 -> 6th launch)
    noop_kernel<<<1, 32>>>();
    noop_kernel<<<1, 32>>>();
    noop_kernel<<<1, 32>>>();
    // 128K weights + 64.25K acts + 32K reduce = 230144 B dynamic smem
    static const int RNN_SMEM = 48 * WSTR * 4 + 8 * 512 * 8;
    cudaFuncSetAttribute(rnn_kernel, cudaFuncAttributeMaxDynamicSharedMemorySize, RNN_SMEM);
    rnn_kernel<<<NCTA, 512, RNN_SMEM>>>(bh);
    readout_kernel<<<T_STEPS, 256>>>(bo, bv, y);
}

// round 13
// speedup vs baseline: 2.2237x; 1.0945x over previous
#include <cuda_runtime.h>
#include <cuda_pipeline.h>
#include <math.h>
#include <stdint.h>

#define T_STEPS 1000
#define BATCH   64
#define IN_DIM  512
#define HID     1024
#define OUT_DIM 64
#define NY      65
#define E_SZ    819
#define ALPHA   0.2f
#define OMALPHA 0.8f
#define NCTA 128
#define OPAD 80
#define WSTR 1028            // padded j-row stride (floats), 16B-aligned rows

__device__ float g_xq[(size_t)T_STEPS * BATCH * HID];     // [t][b][h]  (coalesced for rnn)
__device__ float g_outAll[(size_t)T_STEPS * HID * BATCH]; // [t][j][b]  (readout)
__device__ float g_outT[(size_t)T_STEPS * BATCH * HID];   // [t][b][j]  (rnn broadcast)
__device__ float g_eWhP2[32 * 32 * WSTR];                 // [hgrp][h&31][j pad]
__device__ float g_eWoT[HID * OPAD];                      // [j][o]
__device__ unsigned g_bar[8 * 64];                        // [grp*64]=count, [(4+grp)*64]=flag
                                                          // 1000 flips/group (even) -> replay safe

// ---- acquire/release primitives (no MEMBAR, no L1 flush) ----
__device__ __forceinline__ unsigned atom_add_release(unsigned* p, unsigned v) {
    unsigned r;
    asm volatile("atom.add.release.gpu.global.u32 %0, [%1], %2;"
                 : "=r"(r) : "l"(p), "r"(v) : "memory");
    return r;
}
__device__ __forceinline__ void st_relaxed(unsigned* p, unsigned v) {
    asm volatile("st.relaxed.gpu.global.u32 [%0], %1;" :: "l"(p), "r"(v) : "memory");
}
__device__ __forceinline__ void st_release(unsigned* p, unsigned v) {
    asm volatile("st.release.gpu.global.u32 [%0], %1;" :: "l"(p), "r"(v) : "memory");
}
__device__ __forceinline__ unsigned ld_acquire(unsigned* p) {
    unsigned r;
    asm volatile("ld.acquire.gpu.global.u32 %0, [%1];" : "=r"(r) : "l"(p) : "memory");
    return r;
}

__device__ __forceinline__ unsigned long long pk2(float x, float y) {
    unsigned long long r;
    asm("mov.b64 %0, {%1, %2};" : "=l"(r) : "r"(__float_as_uint(x)), "r"(__float_as_uint(y)));
    return r;
}
__device__ __forceinline__ void upk2(unsigned long long v, float &x, float &y) {
    unsigned xi, yi;
    asm("mov.b64 {%0, %1}, %2;" : "=r"(xi), "=r"(yi) : "l"(v));
    x = __uint_as_float(xi); y = __uint_as_float(yi);
}
__device__ __forceinline__ unsigned long long ffma2(unsigned long long a,
                                                    unsigned long long b,
                                                    unsigned long long c) {
    unsigned long long d;
    asm("fma.rn.f32x2 %0, %1, %2, %3;" : "=l"(d) : "l"(a), "l"(b), "l"(c));
    return d;
}
__device__ __forceinline__ unsigned long long fadd2(unsigned long long a,
                                                    unsigned long long b) {
    unsigned long long d;
    asm("add.rn.f32x2 %0, %1, %2;" : "=l"(d) : "l"(a), "l"(b));
    return d;
}

__global__ void noop_kernel() {}

__global__ void prep_kernel(const float* __restrict__ Wh,
                            const float* __restrict__ Wo,
                            const float* __restrict__ Wv) {
    int idx = blockIdx.x * blockDim.x + threadIdx.x;
    const int N1 = HID * HID;
    if (idx < N1) {
        int h = idx >> 10, j = idx & 1023;
        float v = Wh[idx];
        v = v > 0.f ? v : 0.f;
        float s = (j < E_SZ) ? 1.f : -1.f;
        v = (h == j) ? 0.f : v * s;
        g_eWhP2[(size_t)(h >> 5) * (32 * WSTR) + (size_t)(h & 31) * WSTR + j] = v;
    } else if (idx < N1 + NY * HID) {
        int i2 = idx - N1;
        int o = i2 >> 10, j = i2 & 1023;
        float v = (o < OUT_DIM) ? Wo[o * HID + j] : Wv[j];
        v = v > 0.f ? v : 0.f;
        if (j >= E_SZ) v = 0.f;
        g_eWoT[(size_t)j * OPAD + o] = v;
    }
}

// ---- phase 1: g_xq[t][b][h] = sum_k x[t][b][k]*relu(Wx[h][k])
__global__ __launch_bounds__(256) void xproj_kernel(const float* __restrict__ x,
                                                    const float* __restrict__ Wx) {
    __shared__ float As[16][64];
    __shared__ float Bs[16][128];
    const int t  = blockIdx.y;
    const int h0 = blockIdx.x * 128;
    const int tid = threadIdx.x;
    const int tx = tid & 15;
    const int ty = tid >> 4;

    unsigned long long acc[4][4];
#pragma unroll
    for (int i = 0; i < 4; i++)
#pragma unroll
        for (int p = 0; p < 4; p++) acc[i][p] = 0ull;

    const float* xb = x + (size_t)t * BATCH * IN_DIM;
    const int bb  = tid >> 2;
    const int kk4 = (tid & 3) << 2;
    const int hh  = tid & 127;
    const int kq  = (tid >> 7) << 3;

    for (int k0 = 0; k0 < IN_DIM; k0 += 16) {
        __syncthreads();
        float4 av = *(const float4*)&xb[(size_t)bb * IN_DIM + k0 + kk4];
        As[kk4 + 0][bb] = av.x; As[kk4 + 1][bb] = av.y;
        As[kk4 + 2][bb] = av.z; As[kk4 + 3][bb] = av.w;
        const float* wrow = Wx + (size_t)(h0 + hh) * IN_DIM + k0 + kq;
        float4 w0 = *(const float4*)wrow;
        float4 w1 = *(const float4*)(wrow + 4);
        Bs[kq + 0][hh] = fmaxf(w0.x, 0.f); Bs[kq + 1][hh] = fmaxf(w0.y, 0.f);
        Bs[kq + 2][hh] = fmaxf(w0.z, 0.f); Bs[kq + 3][hh] = fmaxf(w0.w, 0.f);
        Bs[kq + 4][hh] = fmaxf(w1.x, 0.f); Bs[kq + 5][hh] = fmaxf(w1.y, 0.f);
        Bs[kq + 6][hh] = fmaxf(w1.z, 0.f); Bs[kq + 7][hh] = fmaxf(w1.w, 0.f);
        __syncthreads();
#pragma unroll
        for (int kk = 0; kk < 16; kk++) {
            float4 a = *(const float4*)&As[kk][tx << 2];
            ulonglong2 wA = *(const ulonglong2*)&Bs[kk][(ty << 3)];
            ulonglong2 wB = *(const ulonglong2*)&Bs[kk][(ty << 3) + 4];
            unsigned long long a0 = pk2(a.x, a.x), a1 = pk2(a.y, a.y);
            unsigned long long a2 = pk2(a.z, a.z), a3 = pk2(a.w, a.w);
            acc[0][0] = ffma2(a0, wA.x, acc[0][0]); acc[0][1] = ffma2(a0, wA.y, acc[0][1]);
            acc[0][2] = ffma2(a0, wB.x, acc[0][2]); acc[0][3] = ffma2(a0, wB.y, acc[0][3]);
            acc[1][0] = ffma2(a1, wA.x, acc[1][0]); acc[1][1] = ffma2(a1, wA.y, acc[1][1]);
            acc[1][2] = ffma2(a1, wB.x, acc[1][2]); acc[1][3] = ffma2(a1, wB.y, acc[1][3]);
            acc[2][0] = ffma2(a2, wA.x, acc[2][0]); acc[2][1] = ffma2(a2, wA.y, acc[2][1]);
            acc[2][2] = ffma2(a2, wB.x, acc[2][2]); acc[2][3] = ffma2(a2, wB.y, acc[2][3]);
            acc[3][0] = ffma2(a3, wA.x, acc[3][0]); acc[3][1] = ffma2(a3, wA.y, acc[3][1]);
            acc[3][2] = ffma2(a3, wB.x, acc[3][2]); acc[3][3] = ffma2(a3, wB.y, acc[3][3]);
        }
    }
    float* xqT = g_xq + (size_t)t * (BATCH * HID);
#pragma unroll
    for (int i = 0; i < 4; i++) {
        int b = (tx << 2) + i;
#pragma unroll
        for (int p = 0; p < 4; p++) {
            float f0, f1; upk2(acc[i][p], f0, f1);
            int h = h0 + (ty << 3) + (p << 1);
            float2 v2 = make_float2(f0, f1);
            *(float2*)&xqT[(size_t)b * HID + h] = v2;
        }
    }
}

// ---- group barrier: 32 CTAs sharing one b-quarter. No MEMBAR anywhere.
__device__ __forceinline__ void group_barrier(unsigned &sense, int grp) {
    sense ^= 1u;
    __syncthreads();                 // block writes ordered before tid0's release-atom
    if (threadIdx.x == 0) {
        unsigned* cnt  = &g_bar[grp * 64];
        unsigned* flag = &g_bar[(4 + grp) * 64];
        unsigned old = atom_add_release(cnt, 1u);
        if (old == 31u) {
            st_relaxed(cnt, 0u);     // ordered before flag by release below
            st_release(flag, sense);
        } else {
            while (ld_acquire(flag) != sense) { }
        }
    }
    __syncthreads();
}

// ---- phase 2: persistent recurrence. 128 CTAs x 512 threads (4 warps/SMSP).
// CTA = (hgrp: 32 h, b-quarter: 16 b). Weights [32][1028] resident in smem.
// Activation slice staged per step as TWO cp.async groups (j<512 / j>=512);
// each warp computes its lower-64 j after group A, upper-64 after group B.
// Inter-step sync: per-b-quarter barrier over the 32 CTAs that produce the
// consumed slice (release/acquire atomics only).
extern __shared__ float rnn_smem[];
__global__ __launch_bounds__(512, 1) void rnn_kernel(const float* __restrict__ bh) {
    float* sW = rnn_smem;                                   // [32][1028]
    float* sA = rnn_smem + 32 * WSTR;                       // [16][1028]
    unsigned long long* sRed =
        (unsigned long long*)(rnn_smem + 48 * WSTR);        // [8][512]
    float* sOv = sA;                                        // [32][17] (aliases dead sA)

    const int cta = blockIdx.x;
    const int tid = threadIdx.x;
    const int hgrp = cta >> 2;
    const int bqg = cta & 3;             // b-quarter group id
    const int b0 = bqg * 16;
    const int jg = tid >> 6;             // 0..7
    const int i64 = tid & 63;
    const int wh = i64 >> 5;
    const int hg = (i64 >> 2) & 7;
    const int bq = i64 & 3;
    const int h_own = tid & 31;
    const int b_own = tid >> 5;          // 0..15
    const int hOutG = hgrp * 32 + h_own;
    const int bOut = b0 + b_own;
    const int h_s = tid >> 4;            // bounce reader
    const int b_s = tid & 15;
    const int srow = tid >> 5;           // staging row 0..15
    const int scol = (tid & 31) * 4;

    {   // resident weights, once per launch
        const float4* src = (const float4*)(g_eWhP2 + (size_t)hgrp * (32 * WSTR));
        float4* dst = (float4*)sW;
        for (int i = tid; i < 32 * WSTR / 4; i += 512) dst[i] = src[i];
    }

    const float bhv = bh[hOutG];
    unsigned sense = 0;
    float st;
    {   // step 0: out_prev == 0
        float xq = g_xq[(size_t)bOut * HID + hOutG];
        st = ALPHA * (xq + bhv);
        float ov = tanhf(fmaxf(st, 0.f));
        g_outT[(size_t)bOut * HID + hOutG] = ov;
        g_outAll[(size_t)hOutG * 64 + bOut] = ov;  // scattered once, negligible
    }
    group_barrier(sense, bqg);   // barrier #1 (also orders sW staging)

    const float* wR0 = sW + (size_t)(hg + 16 * wh) * WSTR;
    const float* wR1 = sW + (size_t)(hg + 8 + 16 * wh) * WSTR;
    const float* aR0 = sA + (size_t)(bq + 0) * WSTR;
    const float* aR1 = sA + (size_t)(bq + 4) * WSTR;
    const float* aR2 = sA + (size_t)(bq + 8) * WSTR;
    const float* aR3 = sA + (size_t)(bq + 12) * WSTR;
    const int jlo = jg * 64;
    const int jhi = 512 + jg * 64;

    for (int t = 1; t < T_STEPS; t++) {
        {   // stage group A (j < 512) then group B (j >= 512)
            const float* srcRow = g_outT + (size_t)(t - 1) * (BATCH * HID)
                                + (size_t)(b0 + srow) * HID + scol;
            float* dstRow = sA + (size_t)srow * WSTR + scol;
#pragma unroll
            for (int k = 0; k < 4; k++)
                __pipeline_memcpy_async(dstRow + k * 128, srcRow + k * 128, 16);
            __pipeline_commit();
#pragma unroll
            for (int k = 4; k < 8; k++)
                __pipeline_memcpy_async(dstRow + k * 128, srcRow + k * 128, 16);
            __pipeline_commit();
        }
        float xq = g_xq[(size_t)t * (BATCH * HID) + (size_t)bOut * HID + hOutG];

        unsigned long long acc[2][4];
#pragma unroll
        for (int k = 0; k < 2; k++)
#pragma unroll
            for (int m = 0; m < 4; m++) acc[k][m] = 0ull;

        __pipeline_wait_prior(1);   // group A done (this thread)
        __syncthreads();            // -> group A visible block-wide
#pragma unroll 1
        for (int q = 0; q < 16; q++) {
            int j0 = jlo + q * 4;
            ulonglong2 w0 = *(const ulonglong2*)(wR0 + j0);
            ulonglong2 w1 = *(const ulonglong2*)(wR1 + j0);
            ulonglong2 a0 = *(const ulonglong2*)(aR0 + j0);
            ulonglong2 a1 = *(const ulonglong2*)(aR1 + j0);
            ulonglong2 a2 = *(const ulonglong2*)(aR2 + j0);
            ulonglong2 a3 = *(const ulonglong2*)(aR3 + j0);
            acc[0][0] = ffma2(a0.x, w0.x, acc[0][0]); acc[0][0] = ffma2(a0.y, w0.y, acc[0][0]);
            acc[0][1] = ffma2(a1.x, w0.x, acc[0][1]); acc[0][1] = ffma2(a1.y, w0.y, acc[0][1]);
            acc[0][2] = ffma2(a2.x, w0.x, acc[0][2]); acc[0][2] = ffma2(a2.y, w0.y, acc[0][2]);
            acc[0][3] = ffma2(a3.x, w0.x, acc[0][3]); acc[0][3] = ffma2(a3.y, w0.y, acc[0][3]);
            acc[1][0] = ffma2(a0.x, w1.x, acc[1][0]); acc[1][0] = ffma2(a0.y, w1.y, acc[1][0]);
            acc[1][1] = ffma2(a1.x, w1.x, acc[1][1]); acc[1][1] = ffma2(a1.y, w1.y, acc[1][1]);
            acc[1][2] = ffma2(a2.x, w1.x, acc[1][2]); acc[1][2] = ffma2(a2.y, w1.y, acc[1][2]);
            acc[1][3] = ffma2(a3.x, w1.x, acc[1][3]); acc[1][3] = ffma2(a3.y, w1.y, acc[1][3]);
        }
        __pipeline_wait_prior(0);   // group B done
        __syncthreads();
#pragma unroll 1
        for (int q = 0; q < 16; q++) {
            int j0 = jhi + q * 4;
            ulonglong2 w0 = *(const ulonglong2*)(wR0 + j0);
            ulonglong2 w1 = *(const ulonglong2*)(wR1 + j0);
            ulonglong2 a0 = *(const ulonglong2*)(aR0 + j0);
            ulonglong2 a1 = *(const ulonglong2*)(aR1 + j0);
            ulonglong2 a2 = *(const ulonglong2*)(aR2 + j0);
            ulonglong2 a3 = *(const ulonglong2*)(aR3 + j0);
            acc[0][0] = ffma2(a0.x, w0.x, acc[0][0]); acc[0][0] = ffma2(a0.y, w0.y, acc[0][0]);
            acc[0][1] = ffma2(a1.x, w0.x, acc[0][1]); acc[0][1] = ffma2(a1.y, w0.y, acc[0][1]);
            acc[0][2] = ffma2(a2.x, w0.x, acc[0][2]); acc[0][2] = ffma2(a2.y, w0.y, acc[0][2]);
            acc[0][3] = ffma2(a3.x, w0.x, acc[0][3]); acc[0][3] = ffma2(a3.y, w0.y, acc[0][3]);
            acc[1][0] = ffma2(a0.x, w1.x, acc[1][0]); acc[1][0] = ffma2(a0.y, w1.y, acc[1][0]);
            acc[1][1] = ffma2(a1.x, w1.x, acc[1][1]); acc[1][1] = ffma2(a1.y, w1.y, acc[1][1]);
            acc[1][2] = ffma2(a2.x, w1.x, acc[1][2]); acc[1][2] = ffma2(a2.y, w1.y, acc[1][2]);
            acc[1][3] = ffma2(a3.x, w1.x, acc[1][3]); acc[1][3] = ffma2(a3.y, w1.y, acc[1][3]);
        }

        // cross-jg reduction: 8 partial ulls per output; oid = b_local*32 + h_local
#pragma unroll
        for (int k = 0; k < 2; k++)
#pragma unroll
            for (int m = 0; m < 4; m++)
                sRed[jg * 512 + (bq + 4 * m) * 32 + (hg + 8 * k + 16 * wh)] = acc[k][m];
        __syncthreads();            // sRed ready; sA now dead
        unsigned long long s = sRed[tid];
#pragma unroll
        for (int g = 1; g < 8; g++) s = fadd2(s, sRed[g * 512 + tid]);
        float f0, f1; upk2(s, f0, f1);
        float r = f0 + f1;

        st = OMALPHA * st + ALPHA * (xq + r + bhv);
        float ov = tanhf(fmaxf(st, 0.f));
        g_outT[(size_t)t * (BATCH * HID) + (size_t)bOut * HID + hOutG] = ov;  // coalesced
        sOv[h_own * 17 + b_own] = ov;                                        // bounce
        __syncthreads();
        g_outAll[(size_t)t * (HID * BATCH) + (size_t)(hgrp * 32 + h_s) * 64 + b0 + b_s]
            = sOv[h_s * 17 + b_s];                                           // coalesced

        group_barrier(sense, bqg);   // 1000 flips/group (even) -> replay safe
    }
}

// ---- phase 3 (proven): y[t][b][o] = sum_j out[t][j][b]*eWoT[j][o]+bias
__global__ __launch_bounds__(256) void readout_kernel(const float* __restrict__ bo,
                                                      const float* __restrict__ bv,
                                                      float* __restrict__ y) {
    __shared__ float outS[64][64];
    const int t = blockIdx.x;
    const int tid = threadIdx.x;
    const int tx = tid & 15, ty = tid >> 4;
    const int b4 = tx * 4, o4 = ty * 4;
    const float* outT = g_outAll + (size_t)t * (HID * BATCH);

    unsigned long long acc[4][2];
#pragma unroll
    for (int i = 0; i < 4; i++) { acc[i][0] = 0ull; acc[i][1] = 0ull; }
    float accv[4] = {0.f, 0.f, 0.f, 0.f};

    for (int tile = 0; tile < 16; tile++) {
        __syncthreads();
#pragma unroll
        for (int k = 0; k < 4; k++) {
            int fid = tid + k * 256;
            ((float4*)&outS[0][0])[fid] = ((const float4*)(outT + (size_t)tile * 4096))[fid];
        }
        __syncthreads();
#pragma unroll 4
        for (int jj = 0; jj < 64; jj++) {
            int j = tile * 64 + jj;
            float4 ov = *(const float4*)&outS[jj][b4];
            ulonglong2 wq = __ldg((const ulonglong2*)(g_eWoT + (size_t)j * OPAD + o4));
            unsigned long long a0 = pk2(ov.x, ov.x), a1 = pk2(ov.y, ov.y);
            unsigned long long a2 = pk2(ov.z, ov.z), a3 = pk2(ov.w, ov.w);
            acc[0][0] = ffma2(a0, wq.x, acc[0][0]); acc[0][1] = ffma2(a0, wq.y, acc[0][1]);
            acc[1][0] = ffma2(a1, wq.x, acc[1][0]); acc[1][1] = ffma2(a1, wq.y, acc[1][1]);
            acc[2][0] = ffma2(a2, wq.x, acc[2][0]); acc[2][1] = ffma2(a2, wq.y, acc[2][1]);
            acc[3][0] = ffma2(a3, wq.x, acc[3][0]); acc[3][1] = ffma2(a3, wq.y, acc[3][1]);
            if (ty == 0) {
                float w64 = __ldg(g_eWoT + (size_t)j * OPAD + 64);
                accv[0] += ov.x * w64; accv[1] += ov.y * w64;
                accv[2] += ov.z * w64; accv[3] += ov.w * w64;
            }
        }
    }

    float* yt = y + (size_t)t * (BATCH * NY);
    const float bo0 = bo[o4], bo1 = bo[o4 + 1], bo2 = bo[o4 + 2], bo3 = bo[o4 + 3];
#pragma unroll
    for (int i = 0; i < 4; i++) {
        float f0, f1, f2, f3;
        upk2(acc[i][0], f0, f1);
        upk2(acc[i][1], f2, f3);
        float* yr = yt + (size_t)(b4 + i) * NY;
        yr[o4 + 0] = f0 + bo0; yr[o4 + 1] = f1 + bo1;
        yr[o4 + 2] = f2 + bo2; yr[o4 + 3] = f3 + bo3;
        if (ty == 0) yr[64] = accv[i] + bv[0];
    }
}

extern "C" void kernel_launch(void* const* d_in, const int* in_sizes, int n_in,
                              void* d_out, int out_size) {
    const float* x  = (const float*)d_in[0];
    const float* Wx = (const float*)d_in[1];
    const float* Wh = (const float*)d_in[2];
    const float* bh = (const float*)d_in[3];
    const float* Wo = (const float*)d_in[4];
    const float* bo = (const float*)d_in[5];
    const float* Wv = (const float*)d_in[6];
    const float* bv = (const float*)d_in[7];
    float* y = (float*)d_out;
    (void)in_sizes; (void)n_in; (void)out_size;

    {
        int total = HID * HID + NY * HID;
        prep_kernel<<<(total + 255) / 256, 256>>>(Wh, Wo, Wv);
    }
    xproj_kernel<<<dim3(HID / 128, T_STEPS), 256>>>(x, Wx);
    noop_kernel<<<1, 32>>>();   // puts rnn_kernel in the profiled (4th) slot
    static const int RNN_SMEM = 48 * WSTR * 4 + 8 * 512 * 8;  // 230144 B
    cudaFuncSetAttribute(rnn_kernel, cudaFuncAttributeMaxDynamicSharedMemorySize, RNN_SMEM);
    rnn_kernel<<<NCTA, 512, RNN_SMEM>>>(bh);
    readout_kernel<<<T_STEPS, 256>>>(bo, bv, y);
}

// round 14
// speedup vs baseline: 2.2789x; 1.0248x over previous
#include <cuda_runtime.h>
#include <cuda_pipeline.h>
#include <math.h>
#include <stdint.h>

#define T_STEPS 1000
#define BATCH   64
#define IN_DIM  512
#define HID     1024
#define OUT_DIM 64
#define NY      65
#define E_SZ    819
#define ALPHA   0.2f
#define OMALPHA 0.8f
#define NCTA 128
#define OPAD 80
#define WSTR 1028            // weight j-row stride (floats)
#define SAS  132             // staging row stride (floats): 528B -> bq rows land 16B apart mod 128

__device__ float g_xq[(size_t)T_STEPS * BATCH * HID];     // [t][b][h]
__device__ float g_outAll[(size_t)T_STEPS * HID * BATCH]; // [t][j][b]  (readout)
__device__ float g_outT[(size_t)T_STEPS * BATCH * HID];   // [t][b][j]  (rnn broadcast)
__device__ float g_eWhP2[32 * 32 * WSTR];                 // [hgrp][h&31][j pad]
__device__ float g_eWoT[HID * OPAD];                      // [j][o]
__device__ unsigned g_bar[8 * 64];                        // per-b-quarter count/flag (1000 flips, even)

__device__ __forceinline__ unsigned atom_add_release(unsigned* p, unsigned v) {
    unsigned r;
    asm volatile("atom.add.release.gpu.global.u32 %0, [%1], %2;"
                 : "=r"(r) : "l"(p), "r"(v) : "memory");
    return r;
}
__device__ __forceinline__ void st_relaxed(unsigned* p, unsigned v) {
    asm volatile("st.relaxed.gpu.global.u32 [%0], %1;" :: "l"(p), "r"(v) : "memory");
}
__device__ __forceinline__ void st_release(unsigned* p, unsigned v) {
    asm volatile("st.release.gpu.global.u32 [%0], %1;" :: "l"(p), "r"(v) : "memory");
}
__device__ __forceinline__ unsigned ld_acquire(unsigned* p) {
    unsigned r;
    asm volatile("ld.acquire.gpu.global.u32 %0, [%1];" : "=r"(r) : "l"(p) : "memory");
    return r;
}
__device__ __forceinline__ void bar_pair(int id) {
    asm volatile("bar.sync %0, 64;" :: "r"(id) : "memory");
}

__device__ __forceinline__ unsigned long long pk2(float x, float y) {
    unsigned long long r;
    asm("mov.b64 %0, {%1, %2};" : "=l"(r) : "r"(__float_as_uint(x)), "r"(__float_as_uint(y)));
    return r;
}
__device__ __forceinline__ void upk2(unsigned long long v, float &x, float &y) {
    unsigned xi, yi;
    asm("mov.b64 {%0, %1}, %2;" : "=r"(xi), "=r"(yi) : "l"(v));
    x = __uint_as_float(xi); y = __uint_as_float(yi);
}
__device__ __forceinline__ unsigned long long ffma2(unsigned long long a,
                                                    unsigned long long b,
                                                    unsigned long long c) {
    unsigned long long d;
    asm("fma.rn.f32x2 %0, %1, %2, %3;" : "=l"(d) : "l"(a), "l"(b), "l"(c));
    return d;
}
__device__ __forceinline__ unsigned long long fadd2(unsigned long long a,
                                                    unsigned long long b) {
    unsigned long long d;
    asm("add.rn.f32x2 %0, %1, %2;" : "=l"(d) : "l"(a), "l"(b));
    return d;
}

__global__ void noop_kernel() {}

__global__ void prep_kernel(const float* __restrict__ Wh,
                            const float* __restrict__ Wo,
                            const float* __restrict__ Wv) {
    int idx = blockIdx.x * blockDim.x + threadIdx.x;
    const int N1 = HID * HID;
    if (idx < N1) {
        int h = idx >> 10, j = idx & 1023;
        float v = Wh[idx];
        v = v > 0.f ? v : 0.f;
        float s = (j < E_SZ) ? 1.f : -1.f;
        v = (h == j) ? 0.f : v * s;
        g_eWhP2[(size_t)(h >> 5) * (32 * WSTR) + (size_t)(h & 31) * WSTR + j] = v;
    } else if (idx < N1 + NY * HID) {
        int i2 = idx - N1;
        int o = i2 >> 10, j = i2 & 1023;
        float v = (o < OUT_DIM) ? Wo[o * HID + j] : Wv[j];
        v = v > 0.f ? v : 0.f;
        if (j >= E_SZ) v = 0.f;
        g_eWoT[(size_t)j * OPAD + o] = v;
    }
}

// ---- phase 1 (proven): g_xq[t][b][h] = sum_k x[t][b][k]*relu(Wx[h][k])
__global__ __launch_bounds__(256) void xproj_kernel(const float* __restrict__ x,
                                                    const float* __restrict__ Wx) {
    __shared__ float As[16][64];
    __shared__ float Bs[16][128];
    const int t  = blockIdx.y;
    const int h0 = blockIdx.x * 128;
    const int tid = threadIdx.x;
    const int tx = tid & 15;
    const int ty = tid >> 4;

    unsigned long long acc[4][4];
#pragma unroll
    for (int i = 0; i < 4; i++)
#pragma unroll
        for (int p = 0; p < 4; p++) acc[i][p] = 0ull;

    const float* xb = x + (size_t)t * BATCH * IN_DIM;
    const int bb  = tid >> 2;
    const int kk4 = (tid & 3) << 2;
    const int hh  = tid & 127;
    const int kq  = (tid >> 7) << 3;

    for (int k0 = 0; k0 < IN_DIM; k0 += 16) {
        __syncthreads();
        float4 av = *(const float4*)&xb[(size_t)bb * IN_DIM + k0 + kk4];
        As[kk4 + 0][bb] = av.x; As[kk4 + 1][bb] = av.y;
        As[kk4 + 2][bb] = av.z; As[kk4 + 3][bb] = av.w;
        const float* wrow = Wx + (size_t)(h0 + hh) * IN_DIM + k0 + kq;
        float4 w0 = *(const float4*)wrow;
        float4 w1 = *(const float4*)(wrow + 4);
        Bs[kq + 0][hh] = fmaxf(w0.x, 0.f); Bs[kq + 1][hh] = fmaxf(w0.y, 0.f);
        Bs[kq + 2][hh] = fmaxf(w0.z, 0.f); Bs[kq + 3][hh] = fmaxf(w0.w, 0.f);
        Bs[kq + 4][hh] = fmaxf(w1.x, 0.f); Bs[kq + 5][hh] = fmaxf(w1.y, 0.f);
        Bs[kq + 6][hh] = fmaxf(w1.z, 0.f); Bs[kq + 7][hh] = fmaxf(w1.w, 0.f);
        __syncthreads();
#pragma unroll
        for (int kk = 0; kk < 16; kk++) {
            float4 a = *(const float4*)&As[kk][tx << 2];
            ulonglong2 wA = *(const ulonglong2*)&Bs[kk][(ty << 3)];
            ulonglong2 wB = *(const ulonglong2*)&Bs[kk][(ty << 3) + 4];
            unsigned long long a0 = pk2(a.x, a.x), a1 = pk2(a.y, a.y);
            unsigned long long a2 = pk2(a.z, a.z), a3 = pk2(a.w, a.w);
            acc[0][0] = ffma2(a0, wA.x, acc[0][0]); acc[0][1] = ffma2(a0, wA.y, acc[0][1]);
            acc[0][2] = ffma2(a0, wB.x, acc[0][2]); acc[0][3] = ffma2(a0, wB.y, acc[0][3]);
            acc[1][0] = ffma2(a1, wA.x, acc[1][0]); acc[1][1] = ffma2(a1, wA.y, acc[1][1]);
            acc[1][2] = ffma2(a1, wB.x, acc[1][2]); acc[1][3] = ffma2(a1, wB.y, acc[1][3]);
            acc[2][0] = ffma2(a2, wA.x, acc[2][0]); acc[2][1] = ffma2(a2, wA.y, acc[2][1]);
            acc[2][2] = ffma2(a2, wB.x, acc[2][2]); acc[2][3] = ffma2(a2, wB.y, acc[2][3]);
            acc[3][0] = ffma2(a3, wA.x, acc[3][0]); acc[3][1] = ffma2(a3, wA.y, acc[3][1]);
            acc[3][2] = ffma2(a3, wB.x, acc[3][2]); acc[3][3] = ffma2(a3, wB.y, acc[3][3]);
        }
    }
    float* xqT = g_xq + (size_t)t * (BATCH * HID);
#pragma unroll
    for (int i = 0; i < 4; i++) {
        int b = (tx << 2) + i;
#pragma unroll
        for (int p = 0; p < 4; p++) {
            float f0, f1; upk2(acc[i][p], f0, f1);
            int h = h0 + (ty << 3) + (p << 1);
            float2 v2 = make_float2(f0, f1);
            *(float2*)&xqT[(size_t)b * HID + h] = v2;
        }
    }
}

// ---- group barrier: 32 CTAs sharing one b-quarter (proven R13) ----
__device__ __forceinline__ void group_barrier(unsigned &sense, int grp) {
    sense ^= 1u;
    __syncthreads();
    if (threadIdx.x == 0) {
        unsigned* cnt  = &g_bar[grp * 64];
        unsigned* flag = &g_bar[(4 + grp) * 64];
        unsigned old = atom_add_release(cnt, 1u);
        if (old == 31u) {
            st_relaxed(cnt, 0u);
            st_release(flag, sense);
        } else {
            while (ld_acquire(flag) != sense) { }
        }
    }
    __syncthreads();
}

// 16-q compute half: zero-MOV j-paired f32x2
__device__ __forceinline__ void mm_half(const float* wA, const float* wB,
                                        const float* a0p, const float* a1p,
                                        const float* a2p, const float* a3p,
                                        unsigned long long acc[2][4]) {
#pragma unroll 2
    for (int q = 0; q < 16; q++) {
        int j0 = q * 4;
        ulonglong2 w0 = *(const ulonglong2*)(wA + j0);
        ulonglong2 w1 = *(const ulonglong2*)(wB + j0);
        ulonglong2 a0 = *(const ulonglong2*)(a0p + j0);
        ulonglong2 a1 = *(const ulonglong2*)(a1p + j0);
        ulonglong2 a2 = *(const ulonglong2*)(a2p + j0);
        ulonglong2 a3 = *(const ulonglong2*)(a3p + j0);
        acc[0][0] = ffma2(a0.x, w0.x, acc[0][0]); acc[0][0] = ffma2(a0.y, w0.y, acc[0][0]);
        acc[0][1] = ffma2(a1.x, w0.x, acc[0][1]); acc[0][1] = ffma2(a1.y, w0.y, acc[0][1]);
        acc[0][2] = ffma2(a2.x, w0.x, acc[0][2]); acc[0][2] = ffma2(a2.y, w0.y, acc[0][2]);
        acc[0][3] = ffma2(a3.x, w0.x, acc[0][3]); acc[0][3] = ffma2(a3.y, w0.y, acc[0][3]);
        acc[1][0] = ffma2(a0.x, w1.x, acc[1][0]); acc[1][0] = ffma2(a0.y, w1.y, acc[1][0]);
        acc[1][1] = ffma2(a1.x, w1.x, acc[1][1]); acc[1][1] = ffma2(a1.y, w1.y, acc[1][1]);
        acc[1][2] = ffma2(a2.x, w1.x, acc[1][2]); acc[1][2] = ffma2(a2.y, w1.y, acc[1][2]);
        acc[1][3] = ffma2(a3.x, w1.x, acc[1][3]); acc[1][3] = ffma2(a3.y, w1.y, acc[1][3]);
    }
}

// ---- phase 2: persistent recurrence, warp-pair decoupled staging ----
// 128 CTAs x 512 threads. CTA = (hgrp 32h, b-quarter 16b). Weights resident.
// Pair jg (2 warps) privately stages its 16b x 128j slice ({jg*64..}, {512+jg*64..})
// via cp.async and syncs with bar.sync(1+jg, 64) only -> no block-wide lockstep
// in the transfer/compute phase. Block syncs return only for the reduction tail.
extern __shared__ float rnn_smem[];
__global__ __launch_bounds__(512, 1) void rnn_kernel(const float* __restrict__ bh) {
    float* sW = rnn_smem;                           // [32][1028]
    float* sA = rnn_smem + 32 * WSTR;               // 8 pairs x [16][132]
    unsigned long long* sRed = (unsigned long long*)sA;  // [8][512] aliases pairs 0-3
    float* sOv = sA + 4 * (16 * SAS);               // [32][17] aliases pair 4

    const int cta = blockIdx.x;
    const int tid = threadIdx.x;
    const int hgrp = cta >> 2;
    const int bqg = cta & 3;
    const int b0 = bqg * 16;
    const int lane = tid & 31;
    const int jg = tid >> 6;             // pair id 0..7
    const int wh = (tid >> 5) & 1;       // warp within pair
    const int hg = (tid >> 2) & 7;
    const int bq = tid & 3;
    const int h_own = tid & 31;
    const int b_own = tid >> 5;
    const int hOutG = hgrp * 32 + h_own;
    const int bOut = b0 + b_own;
    const int h_s = tid >> 4;            // outAll bounce reader
    const int b_s = tid & 15;

    {   // resident weights, once
        const float4* src = (const float4*)(g_eWhP2 + (size_t)hgrp * (32 * WSTR));
        float4* dst = (float4*)sW;
        for (int i = tid; i < 32 * WSTR / 4; i += 512) dst[i] = src[i];
    }

    const float bhv = bh[hOutG];
    unsigned sense = 0;
    float st;
    {   // step 0: out_prev == 0
        float xq = g_xq[(size_t)bOut * HID + hOutG];
        st = ALPHA * (xq + bhv);
        float ov = tanhf(fmaxf(st, 0.f));
        g_outT[(size_t)bOut * HID + hOutG] = ov;
        g_outAll[(size_t)hOutG * 64 + bOut] = ov;
    }
    group_barrier(sense, bqg);   // also orders sW staging

    float* sAg = sA + jg * (16 * SAS);           // this pair's slice
    const float* wA_lo = sW + (size_t)(hg + 16 * wh) * WSTR + jg * 64;
    const float* wB_lo = sW + (size_t)(hg + 8 + 16 * wh) * WSTR + jg * 64;
    const float* a0p = sAg + (bq + 0) * SAS;
    const float* a1p = sAg + (bq + 4) * SAS;
    const float* a2p = sAg + (bq + 8) * SAS;
    const float* a3p = sAg + (bq + 12) * SAS;
    const int jA = jg * 64;
    const int jB = 512 + jg * 64;
    // staging: warp wh stages rows [8wh, 8wh+8) of the pair slice; 4 chunks/lane/half
    const int srow0 = 8 * wh;

    for (int t = 1; t < T_STEPS; t++) {
        {   // stage half A then half B (per-pair private)
            const float* srcB = g_outT + (size_t)(t - 1) * (BATCH * HID)
                              + (size_t)(b0 + srow0) * HID;
            float* dstB = sAg + srow0 * SAS;
#pragma unroll
            for (int k = 0; k < 4; k++) {
                int cl = lane + 32 * k;
                int row = cl >> 4, col = (cl & 15) * 4;
                __pipeline_memcpy_async(dstB + row * SAS + col,
                                        srcB + (size_t)row * HID + jA + col, 16);
            }
            __pipeline_commit();
#pragma unroll
            for (int k = 0; k < 4; k++) {
                int cl = lane + 32 * k;
                int row = cl >> 4, col = (cl & 15) * 4;
                __pipeline_memcpy_async(dstB + row * SAS + 64 + col,
                                        srcB + (size_t)row * HID + jB + col, 16);
            }
            __pipeline_commit();
        }
        float xq = g_xq[(size_t)t * (BATCH * HID) + (size_t)bOut * HID + hOutG];

        unsigned long long acc[2][4];
#pragma unroll
        for (int k = 0; k < 2; k++)
#pragma unroll
            for (int m = 0; m < 4; m++) acc[k][m] = 0ull;

        __pipeline_wait_prior(1);        // own half-A chunks done
        bar_pair(1 + jg);                // pair's half A complete
        mm_half(wA_lo, wB_lo, a0p, a1p, a2p, a3p, acc);
        __pipeline_wait_prior(0);        // half B done
        bar_pair(1 + jg);
        mm_half(wA_lo + 512, wB_lo + 512, a0p + 64, a1p + 64, a2p + 64, a3p + 64, acc);

        __syncthreads();                 // all pairs done reading sA -> safe to alias
#pragma unroll
        for (int k = 0; k < 2; k++)
#pragma unroll
            for (int m = 0; m < 4; m++)
                sRed[jg * 512 + (bq + 4 * m) * 32 + (hg + 8 * k + 16 * wh)] = acc[k][m];
        __syncthreads();
        unsigned long long s = sRed[tid];
#pragma unroll
        for (int g = 1; g < 8; g++) s = fadd2(s, sRed[g * 512 + tid]);
        float f0, f1; upk2(s, f0, f1);
        float r = f0 + f1;

        st = OMALPHA * st + ALPHA * (xq + r + bhv);
        float ov = tanhf(fmaxf(st, 0.f));
        g_outT[(size_t)t * (BATCH * HID) + (size_t)bOut * HID + hOutG] = ov;  // coalesced
        sOv[h_own * 17 + b_own] = ov;    // pair-4 region: disjoint from sRed
        __syncthreads();
        g_outAll[(size_t)t * (HID * BATCH) + (size_t)(hgrp * 32 + h_s) * 64 + b0 + b_s]
            = sOv[h_s * 17 + b_s];       // coalesced

        group_barrier(sense, bqg);       // 1000 flips/group (even) -> replay safe
    }
}

// ---- phase 3 (proven): y[t][b][o] = sum_j out[t][j][b]*eWoT[j][o]+bias
__global__ __launch_bounds__(256) void readout_kernel(const float* __restrict__ bo,
                                                      const float* __restrict__ bv,
                                                      float* __restrict__ y) {
    __shared__ float outS[64][64];
    const int t = blockIdx.x;
    const int tid = threadIdx.x;
    const int tx = tid & 15, ty = tid >> 4;
    const int b4 = tx * 4, o4 = ty * 4;
    const float* outT = g_outAll + (size_t)t * (HID * BATCH);

    unsigned long long acc[4][2];
#pragma unroll
    for (int i = 0; i < 4; i++) { acc[i][0] = 0ull; acc[i][1] = 0ull; }
    float accv[4] = {0.f, 0.f, 0.f, 0.f};

    for (int tile = 0; tile < 16; tile++) {
        __syncthreads();
#pragma unroll
        for (int k = 0; k < 4; k++) {
            int fid = tid + k * 256;
            ((float4*)&outS[0][0])[fid] = ((const float4*)(outT + (size_t)tile * 4096))[fid];
        }
        __syncthreads();
#pragma unroll 4
        for (int jj = 0; jj < 64; jj++) {
            int j = tile * 64 + jj;
            float4 ov = *(const float4*)&outS[jj][b4];
            ulonglong2 wq = __ldg((const ulonglong2*)(g_eWoT + (size_t)j * OPAD + o4));
            unsigned long long a0 = pk2(ov.x, ov.x), a1 = pk2(ov.y, ov.y);
            unsigned long long a2 = pk2(ov.z, ov.z), a3 = pk2(ov.w, ov.w);
            acc[0][0] = ffma2(a0, wq.x, acc[0][0]); acc[0][1] = ffma2(a0, wq.y, acc[0][1]);
            acc[1][0] = ffma2(a1, wq.x, acc[1][0]); acc[1][1] = ffma2(a1, wq.y, acc[1][1]);
            acc[2][0] = ffma2(a2, wq.x, acc[2][0]); acc[2][1] = ffma2(a2, wq.y, acc[2][1]);
            acc[3][0] = ffma2(a3, wq.x, acc[3][0]); acc[3][1] = ffma2(a3, wq.y, acc[3][1]);
            if (ty == 0) {
                float w64 = __ldg(g_eWoT + (size_t)j * OPAD + 64);
                accv[0] += ov.x * w64; accv[1] += ov.y * w64;
                accv[2] += ov.z * w64; accv[3] += ov.w * w64;
            }
        }
    }

    float* yt = y + (size_t)t * (BATCH * NY);
    const float bo0 = bo[o4], bo1 = bo[o4 + 1], bo2 = bo[o4 + 2], bo3 = bo[o4 + 3];
#pragma unroll
    for (int i = 0; i < 4; i++) {
        float f0, f1, f2, f3;
        upk2(acc[i][0], f0, f1);
        upk2(acc[i][1], f2, f3);
        float* yr = yt + (size_t)(b4 + i) * NY;
        yr[o4 + 0] = f0 + bo0; yr[o4 + 1] = f1 + bo1;
        yr[o4 + 2] = f2 + bo2; yr[o4 + 3] = f3 + bo3;
        if (ty == 0) yr[64] = accv[i] + bv[0];
    }
}

extern "C" void kernel_launch(void* const* d_in, const int* in_sizes, int n_in,
                              void* d_out, int out_size) {
    const float* x  = (const float*)d_in[0];
    const float* Wx = (const float*)d_in[1];
    const float* Wh = (const float*)d_in[2];
    const float* bh = (const float*)d_in[3];
    const float* Wo = (const float*)d_in[4];
    const float* bo = (const float*)d_in[5];
    const float* Wv = (const float*)d_in[6];
    const float* bv = (const float*)d_in[7];
    float* y = (float*)d_out;
    (void)in_sizes; (void)n_in; (void)out_size;

    {
        int total = HID * HID + NY * HID;
        prep_kernel<<<(total + 255) / 256, 256>>>(Wh, Wo, Wv);
    }
    xproj_kernel<<<dim3(HID / 128, T_STEPS), 256>>>(x, Wx);
    noop_kernel<<<1, 32>>>();   // keeps rnn_kernel in the profiled (4th) slot
    // 32*1028 weights + 8*16*132 staging = 49792 floats = 199168 B
    static const int RNN_SMEM = (32 * WSTR + 8 * 16 * SAS) * 4;
    cudaFuncSetAttribute(rnn_kernel, cudaFuncAttributeMaxDynamicSharedMemorySize, RNN_SMEM);
    rnn_kernel<<<NCTA, 512, RNN_SMEM>>>(bh);
    readout_kernel<<<T_STEPS, 256>>>(bo, bv, y);
}